// round 10
// baseline (speedup 1.0000x reference)
#include <cuda_runtime.h>
#include <cuda_bf16.h>
#include <cstdint>

// Problem constants (fixed shapes for this problem instance)
#define NNODES 10000
#define BT 4            // B*T
#define FDIM 128
#define ROW (BT*FDIM)   // 512 floats per node row
#define EMAX 262144
#define MROWS (NNODES*BT)   // 40000 GEMM rows
#define NTILES ((MROWS + 127) / 128)   // 313

// GEMM smem layout (32-bit word offsets into dynamic smem)
#define BKS 132                 // B plane row stride in words (128 kpairs + 4 pad)
#define AKS 36                  // A plane row stride in words (32 kpairs + 4 pad)
#define ABUF (128*AKS)          // 4608 words per A buffer
#define B_HI_OFF 0
#define B_LO_OFF (128*BKS)              // 16896
#define A_HI_OFF (2*128*BKS)            // 33792 (2 buffers)
#define A_LO_OFF (A_HI_OFF + 2*ABUF)    // 43008 (2 buffers)
#define BIAS_OFF (A_LO_OFF + 2*ABUF)    // 52224
#define GSMEM_WORDS (BIAS_OFF + 128)    // 52352
#define GSMEM_BYTES (GSMEM_WORDS*4)     // 209408

// ---------------- device scratch (no allocation allowed) ----------------
__device__ float g_hB[NNODES*ROW];                // fp32 layer-0 output (agg1 input)
// bf16-split A-operand planes: [m][64 kpairs] each
__device__ uint32_t g_XAhi[MROWS*64];  // feat (layer0 X0)
__device__ uint32_t g_XAlo[MROWS*64];
__device__ uint32_t g_XBhi[MROWS*64];  // g_hB  (layer1 X0)
__device__ uint32_t g_XBlo[MROWS*64];
__device__ uint32_t g_AGhi[MROWS*64];  // agg output (both layers)
__device__ uint32_t g_AGlo[MROWS*64];
__device__ uint32_t g_WThi[2*128*128];  // per layer: [n][kpair] bf16x2 hi plane
__device__ uint32_t g_WTlo[2*128*128];  // per layer: [n][kpair] bf16x2 lo plane
__device__ int   g_deg[NNODES];
__device__ int   g_cursor[NNODES];
__device__ int   g_off[NNODES+1];
__device__ float g_invdeg[NNODES];
__device__ int   g_esrc_sorted[EMAX];
__device__ int   g_tilectr[2];

// ---------------- helpers ----------------
__device__ __forceinline__ uint32_t smem_u32(const void* p) {
    uint32_t a;
    asm("{ .reg .u64 t; cvta.to.shared.u64 t, %1; cvt.u32.u64 %0, t; }"
        : "=r"(a) : "l"(p));
    return a;
}

__device__ __forceinline__ void split2(float a, float b, uint32_t& hi, uint32_t& lo) {
    __nv_bfloat16 ha = __float2bfloat16_rn(a);
    __nv_bfloat16 hb = __float2bfloat16_rn(b);
    float ra = a - __bfloat162float(ha);
    float rb = b - __bfloat162float(hb);
    __nv_bfloat16 la = __float2bfloat16_rn(ra);
    __nv_bfloat16 lb = __float2bfloat16_rn(rb);
    hi = ((uint32_t)__bfloat16_as_ushort(hb) << 16) | (uint32_t)__bfloat16_as_ushort(ha);
    lo = ((uint32_t)__bfloat16_as_ushort(lb) << 16) | (uint32_t)__bfloat16_as_ushort(la);
}

__device__ __forceinline__ void mma_bf16(float* c, const uint32_t* a,
                                         uint32_t b0, uint32_t b1) {
    asm volatile(
        "mma.sync.aligned.m16n8k16.row.col.f32.bf16.bf16.f32 "
        "{%0,%1,%2,%3}, {%4,%5,%6,%7}, {%8,%9}, {%0,%1,%2,%3};"
        : "+f"(c[0]), "+f"(c[1]), "+f"(c[2]), "+f"(c[3])
        : "r"(a[0]), "r"(a[1]), "r"(a[2]), "r"(a[3]), "r"(b0), "r"(b1));
}

__device__ __forceinline__ void ldsm4(uint32_t& r0, uint32_t& r1,
                                      uint32_t& r2, uint32_t& r3, uint32_t addr) {
    asm volatile("ldmatrix.sync.aligned.m8n8.x4.shared.b16 {%0,%1,%2,%3}, [%4];"
                 : "=r"(r0), "=r"(r1), "=r"(r2), "=r"(r3) : "r"(addr));
}

#define CP_ASYNC16(dst, src) \
    asm volatile("cp.async.cg.shared.global [%0], [%1], 16;" \
                 :: "r"(dst), "l"(src))
#define CP_COMMIT() asm volatile("cp.async.commit_group;")
#define CP_WAIT_ALL() asm volatile("cp.async.wait_group 0;")

// ---------------- setup kernels ----------------
// Fused: degree histogram + weight pre-split + feat pre-split planes.
__global__ void setup_kernel(const int* __restrict__ edst, int E,
                             const float* __restrict__ Wself,
                             const float* __restrict__ Wneigh,
                             const float* __restrict__ feat) {
    int gidx = blockIdx.x * blockDim.x + threadIdx.x;
    int stride = gridDim.x * blockDim.x;

    // degree (4 edges/thread via int4)
    int n4 = E >> 2;
    if (gidx < n4) {
        int4 v = ((const int4*)edst)[gidx];
        atomicAdd(&g_deg[v.x], 1);
        atomicAdd(&g_deg[v.y], 1);
        atomicAdd(&g_deg[v.z], 1);
        atomicAdd(&g_deg[v.w], 1);
    }
    if (gidx == 0) {
        for (int e = n4 * 4; e < E; e++) atomicAdd(&g_deg[edst[e]], 1);
    }

    // weight pre-split: 2*128*128 = 32768 kpairs
    if (gidx < 2 * 128 * 128) {
        int l = gidx >> 14;
        int rem = gidx & 16383;
        int n = rem >> 7;
        int kp = rem & 127;
        float w0, w1;
        if (kp < 64) {
            int k = 2 * kp;
            w0 = Wself[l * 16384 + k * 128 + n];
            w1 = Wself[l * 16384 + (k + 1) * 128 + n];
        } else {
            int k = 2 * kp - 128;
            w0 = Wneigh[l * 16384 + k * 128 + n];
            w1 = Wneigh[l * 16384 + (k + 1) * 128 + n];
        }
        uint32_t hi, lo;
        split2(w0, w1, hi, lo);
        g_WThi[gidx] = hi;
        g_WTlo[gidx] = lo;
    }

    // feat pre-split: MROWS*32 float4s -> XA planes [m][64 kpairs]
    const float4* fv = (const float4*)feat;
    for (int j = gidx; j < MROWS * 32; j += stride) {
        int m = j >> 5;
        int f4 = j & 31;
        int node = m >> 2;
        int bt = m & 3;
        float4 v = fv[(bt * NNODES + node) * 32 + f4];
        uint32_t h0, l0, h1, l1;
        split2(v.x, v.y, h0, l0);
        split2(v.z, v.w, h1, l1);
        *(uint2*)&g_XAhi[(size_t)m * 64 + 2 * f4] = make_uint2(h0, h1);
        *(uint2*)&g_XAlo[(size_t)m * 64 + 2 * f4] = make_uint2(l0, l1);
    }
}

// fast single-CTA scan: 10 elems/thread + warp/block shuffle scan
__global__ void __launch_bounds__(1024) scan_kernel(int E) {
    __shared__ int wsum[32];
    int tid = threadIdx.x;
    int lane = tid & 31;
    int w = tid >> 5;
    int base = tid * 10;
    int d[10];
    int tot = 0;
#pragma unroll
    for (int j = 0; j < 10; j++) {
        int idx = base + j;
        d[j] = (idx < NNODES) ? g_deg[idx] : 0;
        tot += d[j];
    }
    int inc = tot;
#pragma unroll
    for (int off = 1; off < 32; off <<= 1) {
        int nv = __shfl_up_sync(0xffffffffu, inc, off);
        if (lane >= off) inc += nv;
    }
    if (lane == 31) wsum[w] = inc;
    __syncthreads();
    if (w == 0) {
        int v = wsum[lane];
        int i2 = v;
#pragma unroll
        for (int off = 1; off < 32; off <<= 1) {
            int nv = __shfl_up_sync(0xffffffffu, i2, off);
            if (lane >= off) i2 += nv;
        }
        wsum[lane] = i2 - v;
    }
    __syncthreads();
    int run = wsum[w] + inc - tot;
#pragma unroll
    for (int j = 0; j < 10; j++) {
        int idx = base + j;
        if (idx < NNODES) {
            g_off[idx] = run;
            g_invdeg[idx] = (d[j] > 0) ? (1.0f / (float)d[j]) : 0.0f;
        }
        run += d[j];
    }
    if (tid == 0) g_off[NNODES] = E;
}

__global__ void bucket_kernel(const int* __restrict__ esrc,
                              const int* __restrict__ edst, int E) {
    int e4 = blockIdx.x * blockDim.x + threadIdx.x;
    int n4 = E >> 2;
    if (e4 < n4) {
        int4 s = ((const int4*)esrc)[e4];
        int4 d = ((const int4*)edst)[e4];
        int p;
        p = g_off[d.x] + atomicAdd(&g_cursor[d.x], 1); g_esrc_sorted[p] = s.x;
        p = g_off[d.y] + atomicAdd(&g_cursor[d.y], 1); g_esrc_sorted[p] = s.y;
        p = g_off[d.z] + atomicAdd(&g_cursor[d.z], 1); g_esrc_sorted[p] = s.z;
        p = g_off[d.w] + atomicAdd(&g_cursor[d.w], 1); g_esrc_sorted[p] = s.w;
    }
    if (e4 == 0) {
        for (int e = n4 * 4; e < E; e++) {
            int dn = edst[e];
            int p = g_off[dn] + atomicAdd(&g_cursor[dn], 1);
            g_esrc_sorted[p] = esrc[e];
        }
    }
}

// ---------------- per-node aggregation (128 threads, tt in 0..127) --------
// Emits bf16-split planes g_AGhi/g_AGlo directly (fp32 accumulate, split at end).
__device__ __forceinline__ void agg_node(const float* __restrict__ feat,
                                         int src_sel, int n, int tt) {
    int s = g_off[n];
    int e = g_off[n + 1];
    float4 a0 = make_float4(0.f, 0.f, 0.f, 0.f);
    float4 a1 = make_float4(0.f, 0.f, 0.f, 0.f);
    float4 a2 = make_float4(0.f, 0.f, 0.f, 0.f);
    float4 a3 = make_float4(0.f, 0.f, 0.f, 0.f);
    int i = s;
    if (src_sel == 0) {
        const float4* hv = (const float4*)feat;
        int bt = tt >> 5;
        int f4 = tt & 31;
        int boff = bt * NNODES * 32 + f4;
        for (; i + 3 < e; i += 4) {
            int s0 = g_esrc_sorted[i];
            int s1 = g_esrc_sorted[i + 1];
            int s2 = g_esrc_sorted[i + 2];
            int s3 = g_esrc_sorted[i + 3];
            float4 v0 = hv[boff + s0 * 32];
            float4 v1 = hv[boff + s1 * 32];
            float4 v2 = hv[boff + s2 * 32];
            float4 v3 = hv[boff + s3 * 32];
            a0.x += v0.x; a0.y += v0.y; a0.z += v0.z; a0.w += v0.w;
            a1.x += v1.x; a1.y += v1.y; a1.z += v1.z; a1.w += v1.w;
            a2.x += v2.x; a2.y += v2.y; a2.z += v2.z; a2.w += v2.w;
            a3.x += v3.x; a3.y += v3.y; a3.z += v3.z; a3.w += v3.w;
        }
        for (; i < e; i++) {
            int s0 = g_esrc_sorted[i];
            float4 v0 = hv[boff + s0 * 32];
            a0.x += v0.x; a0.y += v0.y; a0.z += v0.z; a0.w += v0.w;
        }
    } else {
        const float4* hv = (const float4*)g_hB;
        for (; i + 3 < e; i += 4) {
            int s0 = g_esrc_sorted[i];
            int s1 = g_esrc_sorted[i + 1];
            int s2 = g_esrc_sorted[i + 2];
            int s3 = g_esrc_sorted[i + 3];
            float4 v0 = hv[s0 * 128 + tt];
            float4 v1 = hv[s1 * 128 + tt];
            float4 v2 = hv[s2 * 128 + tt];
            float4 v3 = hv[s3 * 128 + tt];
            a0.x += v0.x; a0.y += v0.y; a0.z += v0.z; a0.w += v0.w;
            a1.x += v1.x; a1.y += v1.y; a1.z += v1.z; a1.w += v1.w;
            a2.x += v2.x; a2.y += v2.y; a2.z += v2.z; a2.w += v2.w;
            a3.x += v3.x; a3.y += v3.y; a3.z += v3.z; a3.w += v3.w;
        }
        for (; i < e; i++) {
            int s0 = g_esrc_sorted[i];
            float4 v0 = hv[s0 * 128 + tt];
            a0.x += v0.x; a0.y += v0.y; a0.z += v0.z; a0.w += v0.w;
        }
    }
    float inv = g_invdeg[n];
    float4 r;
    r.x = (a0.x + a1.x + a2.x + a3.x) * inv;
    r.y = (a0.y + a1.y + a2.y + a3.y) * inv;
    r.z = (a0.z + a1.z + a2.z + a3.z) * inv;
    r.w = (a0.w + a1.w + a2.w + a3.w) * inv;
    // split & store to planes: m = n*4+bt, kpairs 2*f4, 2*f4+1
    int bt = tt >> 5;
    int f4 = tt & 31;
    size_t m = (size_t)n * 4 + bt;
    uint32_t h0, l0, h1, l1;
    split2(r.x, r.y, h0, l0);
    split2(r.z, r.w, h1, l1);
    *(uint2*)&g_AGhi[m * 64 + 2 * f4] = make_uint2(h0, h1);
    *(uint2*)&g_AGlo[m * 64 + 2 * f4] = make_uint2(l0, l1);
}

// 2 nodes per 256-thread CTA (parallel halves)
__global__ void __launch_bounds__(256) agg_kernel(const float* __restrict__ feat,
                                                  int src_sel) {
    int half = threadIdx.x >> 7;
    int tt = threadIdx.x & 127;
    int n = blockIdx.x * 2 + half;
    if (n < NNODES) agg_node(feat, src_sel, n, tt);
}

// ---------------- persistent bf16x2-split GEMM (cp.async + ldmatrix) ------
// out[m][n] = sum_k X[m][k]*W[k][n] + b[n]; M=40000, K=256, N=128.
// A operands are pre-split planes in global; staging = pure cp.async copies.
__global__ void __launch_bounds__(256) gemm_mma(int layer,
                                                const float* __restrict__ bias,
                                                float* __restrict__ out_ext) {
    extern __shared__ uint32_t sm[];
    __shared__ int s_tile;
    uint32_t* Bhi = sm + B_HI_OFF;
    uint32_t* Blo = sm + B_LO_OFF;
    float* sbias = (float*)(sm + BIAS_OFF);

    int tid = threadIdx.x;
    int lane = tid & 31;
    int warp = tid >> 5;
    int g = lane >> 2;
    int t = lane & 3;
    int wr = (warp & 3) * 32;
    int wc = (warp >> 2) * 64;
    uint32_t smbase = smem_u32(sm);

    // ldmatrix lane address components (word offsets)
    int am = lane >> 3;
    int ar = lane & 7;
    int a_base = (wr + ((am & 1) << 3) + ar) * AKS + ((am >> 1) << 2);
    int b_base = (wc + ((lane >> 4) << 3) + ar) * BKS + (((lane >> 3) & 1) << 2);

    if (tid < 128) sbias[tid] = bias[tid];

    // stage B once
    const uint4* bhv = (const uint4*)(g_WThi + layer * 128 * 128);
    const uint4* blv = (const uint4*)(g_WTlo + layer * 128 * 128);
#pragma unroll
    for (int i = 0; i < 16; i++) {
        int lin = tid + i * 256;
        int n = lin >> 5;
        int j = lin & 31;
        *(uint4*)&Bhi[n * BKS + 4 * j] = bhv[lin];
        *(uint4*)&Blo[n * BKS + 4 * j] = blv[lin];
    }

    const uint32_t* XH = (layer == 0) ? g_XAhi : g_XBhi;
    const uint32_t* XL = (layer == 0) ? g_XAlo : g_XBlo;

    // per-thread fixed staging slots: 4 (row,q) pairs
    int srow[4], sq[4];
#pragma unroll
    for (int i = 0; i < 4; i++) {
        int lin = tid + i * 256;
        srow[i] = lin >> 3;
        sq[i] = lin & 7;
    }

    while (true) {
        if (tid == 0) s_tile = atomicAdd(&g_tilectr[layer], 1);
        __syncthreads();
        int tnum = s_tile;
        if (tnum >= NTILES) break;
        int tile = tnum * 128;

        float acc[2][8][4];
#pragma unroll
        for (int rb = 0; rb < 2; rb++)
#pragma unroll
            for (int nb = 0; nb < 8; nb++)
#pragma unroll
                for (int c = 0; c < 4; c++) acc[rb][nb][c] = 0.f;

        // issue chunk 0 into buf 0
        {
#pragma unroll
            for (int i = 0; i < 4; i++) {
                int m = tile + srow[i];
                if (m >= MROWS) m = MROWS - 1;
                size_t so = (size_t)m * 64 + sq[i] * 4;
                uint32_t doff = 4u * (srow[i] * AKS + sq[i] * 4);
                CP_ASYNC16(smbase + 4u * A_HI_OFF + doff, XH + so);
                CP_ASYNC16(smbase + 4u * A_LO_OFF + doff, XL + so);
            }
            CP_COMMIT();
        }

        for (int kc = 0; kc < 4; kc++) {
            int buf = kc & 1;
            CP_WAIT_ALL();
            __syncthreads();

            if (kc < 3) {
                int nbuf = (kc + 1) & 1;
                const uint32_t* sH;
                const uint32_t* sL;
                int off;
                if (kc + 1 < 2) { sH = XH; sL = XL; off = (kc + 1) * 32; }
                else            { sH = g_AGhi; sL = g_AGlo; off = (kc - 1) * 32; }
#pragma unroll
                for (int i = 0; i < 4; i++) {
                    int m = tile + srow[i];
                    if (m >= MROWS) m = MROWS - 1;
                    size_t so = (size_t)m * 64 + off + sq[i] * 4;
                    uint32_t doff = 4u * (nbuf * ABUF + srow[i] * AKS + sq[i] * 4);
                    CP_ASYNC16(smbase + 4u * A_HI_OFF + doff, sH + so);
                    CP_ASYNC16(smbase + 4u * A_LO_OFF + doff, sL + so);
                }
                CP_COMMIT();
            }

            uint32_t ahi_addr = smbase + 4u * (A_HI_OFF + buf * ABUF + a_base);
            uint32_t alo_addr = smbase + 4u * (A_LO_OFF + buf * ABUF + a_base);
#pragma unroll
            for (int ks = 0; ks < 4; ks++) {
                int kb = ks * 8;
                int gb = kc * 32 + kb;
                uint32_t ah[2][4], al[2][4];
#pragma unroll
                for (int rb = 0; rb < 2; rb++) {
                    uint32_t off = 4u * (rb * 16 * AKS + kb);
                    ldsm4(ah[rb][0], ah[rb][1], ah[rb][2], ah[rb][3], ahi_addr + off);
                    ldsm4(al[rb][0], al[rb][1], al[rb][2], al[rb][3], alo_addr + off);
                }
#pragma unroll
                for (int nb = 0; nb < 8; nb += 2) {
                    uint32_t bw = smbase + 4u * (b_base + nb * 8 * BKS + gb);
                    uint32_t bh[4], bl[4];
                    ldsm4(bh[0], bh[1], bh[2], bh[3], bw + 4u * B_HI_OFF);
                    ldsm4(bl[0], bl[1], bl[2], bl[3], bw + 4u * B_LO_OFF);
#pragma unroll
                    for (int rb = 0; rb < 2; rb++) {
                        mma_bf16(acc[rb][nb], ah[rb], bh[0], bh[1]);
                        mma_bf16(acc[rb][nb], al[rb], bh[0], bh[1]);
                        mma_bf16(acc[rb][nb], ah[rb], bl[0], bl[1]);
                        mma_bf16(acc[rb][nb + 1], ah[rb], bh[2], bh[3]);
                        mma_bf16(acc[rb][nb + 1], al[rb], bh[2], bh[3]);
                        mma_bf16(acc[rb][nb + 1], ah[rb], bl[2], bl[3]);
                    }
                }
            }
        }

        // epilogue
#pragma unroll
        for (int rb = 0; rb < 2; rb++) {
#pragma unroll
            for (int h = 0; h < 2; h++) {
                int m = tile + wr + rb * 16 + g + h * 8;
                if (m < MROWS) {
#pragma unroll
                    for (int nb = 0; nb < 8; nb++) {
                        int col = wc + nb * 8 + 2 * t;
                        float2 vv;
                        vv.x = acc[rb][nb][h * 2 + 0] + sbias[col];
                        vv.y = acc[rb][nb][h * 2 + 1] + sbias[col + 1];
                        if (layer == 0) {
                            *(float2*)(g_hB + (size_t)m * 128 + col) = vv;
                            uint32_t hh, ll;
                            split2(vv.x, vv.y, hh, ll);
                            g_XBhi[(size_t)m * 64 + (col >> 1)] = hh;
                            g_XBlo[(size_t)m * 64 + (col >> 1)] = ll;
                        } else {
                            int n = m >> 2;
                            int bt = m & 3;
                            *(float2*)(out_ext + ((size_t)bt * NNODES + n) * 128 + col) = vv;
                        }
                    }
                }
            }
        }
        __syncthreads();   // protect s_tile / buffers before next claim
    }
}

// ---------------- launch ----------------
extern "C" void kernel_launch(void* const* d_in, const int* in_sizes, int n_in,
                              void* d_out, int out_size) {
    const float* feat   = (const float*)d_in[0];
    const float* Wself  = (const float*)d_in[1];
    const float* Wneigh = (const float*)d_in[2];
    const float* bias   = (const float*)d_in[3];
    const int*   esrc   = (const int*)d_in[4];
    const int*   edst   = (const int*)d_in[5];
    int E = in_sizes[4];

    cudaFuncSetAttribute(gemm_mma, cudaFuncAttributeMaxDynamicSharedMemorySize,
                         GSMEM_BYTES);

    void *p_deg, *p_cur, *p_ctr;
    cudaGetSymbolAddress(&p_deg, g_deg);
    cudaGetSymbolAddress(&p_cur, g_cursor);
    cudaGetSymbolAddress(&p_ctr, g_tilectr);
    cudaMemsetAsync(p_deg, 0, NNODES * sizeof(int));
    cudaMemsetAsync(p_cur, 0, NNODES * sizeof(int));
    cudaMemsetAsync(p_ctr, 0, 2 * sizeof(int));

    setup_kernel<<<((E / 4) + 255) / 256, 256>>>(edst, E, Wself, Wneigh, feat);
    scan_kernel<<<1, 1024>>>(E);
    bucket_kernel<<<((E / 4) + 255) / 256, 256>>>(esrc, edst, E);

    // layer 0: agg(feat) -> AG planes, gemm(XA, AG) -> g_hB + XB planes
    agg_kernel<<<(NNODES + 1) / 2, 256>>>(feat, 0);
    gemm_mma<<<148, 256, GSMEM_BYTES>>>(0, bias, (float*)d_out);

    // layer 1: agg(g_hB) -> AG planes, gemm(XB, AG) -> d_out ([B,T,N,F])
    agg_kernel<<<(NNODES + 1) / 2, 256>>>(feat, 1);
    gemm_mma<<<148, 256, GSMEM_BYTES>>>(1, bias + 128, (float*)d_out);
}

// round 12
// speedup vs baseline: 1.0983x; 1.0983x over previous
#include <cuda_runtime.h>
#include <cuda_bf16.h>
#include <cstdint>

// Problem constants (fixed shapes for this problem instance)
#define NNODES 10000
#define BT 4            // B*T
#define FDIM 128
#define ROW (BT*FDIM)   // 512 floats per node row
#define EMAX 262144
#define MROWS (NNODES*BT)   // 40000 GEMM rows
#define NTILES ((MROWS + 127) / 128)   // 313

// GEMM smem layout (32-bit word offsets into dynamic smem)
#define BKS 132                 // B plane row stride in words (128 kpairs + 4 pad)
#define AKS 36                  // A plane row stride in words (32 kpairs + 4 pad)
#define ABUF (128*AKS)          // 4608 words per A buffer
#define B_HI_OFF 0
#define B_LO_OFF (128*BKS)              // 16896
#define A_HI_OFF (2*128*BKS)            // 33792 (2 buffers)
#define A_LO_OFF (A_HI_OFF + 2*ABUF)    // 43008 (2 buffers)
#define BIAS_OFF (A_LO_OFF + 2*ABUF)    // 52224
#define GSMEM_WORDS (BIAS_OFF + 128)    // 52352
#define GSMEM_BYTES (GSMEM_WORDS*4)     // 209408

// ---------------- device scratch (no allocation allowed) ----------------
__device__ float g_hB[NNODES*ROW];
__device__ float g_agg[NNODES*ROW];
__device__ uint32_t g_WThi[2*128*128];  // per layer: [n][kpair] bf16x2 hi plane
__device__ uint32_t g_WTlo[2*128*128];  // per layer: [n][kpair] bf16x2 lo plane
__device__ int   g_deg[NNODES];
__device__ int   g_cursor[NNODES];
__device__ int   g_off[NNODES+1];
__device__ float g_invdeg[NNODES];
__device__ int   g_esrc_sorted[EMAX];
__device__ int   g_tilectr[2];
__device__ int   g_sync[2];

// ---------------- helpers ----------------
__device__ __forceinline__ uint32_t smem_u32(const void* p) {
    uint32_t a;
    asm("{ .reg .u64 t; cvta.to.shared.u64 t, %1; cvt.u32.u64 %0, t; }"
        : "=r"(a) : "l"(p));
    return a;
}

__device__ __forceinline__ void split2(float a, float b, uint32_t& hi, uint32_t& lo) {
    __nv_bfloat16 ha = __float2bfloat16_rn(a);
    __nv_bfloat16 hb = __float2bfloat16_rn(b);
    float ra = a - __bfloat162float(ha);
    float rb = b - __bfloat162float(hb);
    __nv_bfloat16 la = __float2bfloat16_rn(ra);
    __nv_bfloat16 lb = __float2bfloat16_rn(rb);
    hi = ((uint32_t)__bfloat16_as_ushort(hb) << 16) | (uint32_t)__bfloat16_as_ushort(ha);
    lo = ((uint32_t)__bfloat16_as_ushort(lb) << 16) | (uint32_t)__bfloat16_as_ushort(la);
}

__device__ __forceinline__ void mma_bf16(float* c, const uint32_t* a,
                                         uint32_t b0, uint32_t b1) {
    asm volatile(
        "mma.sync.aligned.m16n8k16.row.col.f32.bf16.bf16.f32 "
        "{%0,%1,%2,%3}, {%4,%5,%6,%7}, {%8,%9}, {%0,%1,%2,%3};"
        : "+f"(c[0]), "+f"(c[1]), "+f"(c[2]), "+f"(c[3])
        : "r"(a[0]), "r"(a[1]), "r"(a[2]), "r"(a[3]), "r"(b0), "r"(b1));
}

__device__ __forceinline__ void ldsm4(uint32_t& r0, uint32_t& r1,
                                      uint32_t& r2, uint32_t& r3, uint32_t addr) {
    asm volatile("ldmatrix.sync.aligned.m8n8.x4.shared.b16 {%0,%1,%2,%3}, [%4];"
                 : "=r"(r0), "=r"(r1), "=r"(r2), "=r"(r3) : "r"(addr));
}

// ---------------- setup kernels ----------------
// #1: weight pre-split (independent of edges)
__global__ void wt_kernel(const float* __restrict__ Wself,
                          const float* __restrict__ Wneigh) {
    int idx = blockIdx.x * blockDim.x + threadIdx.x;   // 2*128*128 = 32768 kpairs
    if (idx >= 2 * 128 * 128) return;
    int l = idx >> 14;
    int rem = idx & 16383;
    int n = rem >> 7;
    int kp = rem & 127;
    float w0, w1;
    if (kp < 64) {
        int k = 2 * kp;
        w0 = Wself[l * 16384 + k * 128 + n];
        w1 = Wself[l * 16384 + (k + 1) * 128 + n];
    } else {
        int k = 2 * kp - 128;
        w0 = Wneigh[l * 16384 + k * 128 + n];
        w1 = Wneigh[l * 16384 + (k + 1) * 128 + n];
    }
    uint32_t hi, lo;
    split2(w0, w1, hi, lo);
    g_WThi[idx] = hi;
    g_WTlo[idx] = lo;
}

// #2: fused CSR build: degree -> (grid spin barrier) -> scan (block 0)
//     -> (flag barrier) -> bucket. Grid 148x1024, 1 CTA/SM, all resident.
__global__ void __launch_bounds__(1024) csr_kernel(const int* __restrict__ esrc,
                                                   const int* __restrict__ edst,
                                                   int E) {
    int tid = threadIdx.x;
    int gid = blockIdx.x * 1024 + tid;
    int nthreads = gridDim.x * 1024;
    int n4 = E >> 2;

    // --- phase 1: degree histogram (int4) ---
    for (int j = gid; j < n4; j += nthreads) {
        int4 v = ((const int4*)edst)[j];
        atomicAdd(&g_deg[v.x], 1);
        atomicAdd(&g_deg[v.y], 1);
        atomicAdd(&g_deg[v.z], 1);
        atomicAdd(&g_deg[v.w], 1);
    }
    if (gid == 0) {
        for (int e = n4 * 4; e < E; e++) atomicAdd(&g_deg[edst[e]], 1);
    }
    __threadfence();
    __syncthreads();
    if (tid == 0) {
        atomicAdd(&g_sync[0], 1);
        while (atomicAdd(&g_sync[0], 0) < (int)gridDim.x) __nanosleep(64);
    }
    __syncthreads();

    // --- phase 2: exclusive scan + inv_deg (block 0 only, 1024 threads) ---
    if (blockIdx.x == 0) {
        __shared__ int wsum[32];
        int lane = tid & 31;
        int w = tid >> 5;
        int base = tid * 10;
        int d[10];
        int tot = 0;
#pragma unroll
        for (int j = 0; j < 10; j++) {
            int idx = base + j;
            d[j] = (idx < NNODES) ? g_deg[idx] : 0;
            tot += d[j];
        }
        int inc = tot;
#pragma unroll
        for (int off = 1; off < 32; off <<= 1) {
            int nv = __shfl_up_sync(0xffffffffu, inc, off);
            if (lane >= off) inc += nv;
        }
        if (lane == 31) wsum[w] = inc;
        __syncthreads();
        if (w == 0) {
            int v = wsum[lane];
            int i2 = v;
#pragma unroll
            for (int off = 1; off < 32; off <<= 1) {
                int nv = __shfl_up_sync(0xffffffffu, i2, off);
                if (lane >= off) i2 += nv;
            }
            wsum[lane] = i2 - v;
        }
        __syncthreads();
        int run = wsum[w] + inc - tot;
#pragma unroll
        for (int j = 0; j < 10; j++) {
            int idx = base + j;
            if (idx < NNODES) {
                g_off[idx] = run;
                g_invdeg[idx] = (d[j] > 0) ? (1.0f / (float)d[j]) : 0.0f;
            }
            run += d[j];
        }
        if (tid == 0) g_off[NNODES] = E;
        __threadfence();
        __syncthreads();
        if (tid == 0) atomicExch(&g_sync[1], 1);
    }
    if (tid == 0) {
        while (atomicAdd(&g_sync[1], 0) == 0) __nanosleep(64);
    }
    __syncthreads();

    // --- phase 3: bucket scatter ---
    for (int j = gid; j < n4; j += nthreads) {
        int4 s = ((const int4*)esrc)[j];
        int4 d = ((const int4*)edst)[j];
        int p;
        p = g_off[d.x] + atomicAdd(&g_cursor[d.x], 1); g_esrc_sorted[p] = s.x;
        p = g_off[d.y] + atomicAdd(&g_cursor[d.y], 1); g_esrc_sorted[p] = s.y;
        p = g_off[d.z] + atomicAdd(&g_cursor[d.z], 1); g_esrc_sorted[p] = s.z;
        p = g_off[d.w] + atomicAdd(&g_cursor[d.w], 1); g_esrc_sorted[p] = s.w;
    }
    if (gid == 0) {
        for (int e = n4 * 4; e < E; e++) {
            int dn = edst[e];
            int p = g_off[dn] + atomicAdd(&g_cursor[dn], 1);
            g_esrc_sorted[p] = esrc[e];
        }
    }
}

// ---------------- mean aggregation: one CTA per dst node, 8-wide MLP -----
__global__ void __launch_bounds__(128) agg_kernel(const float* __restrict__ feat,
                                                  int src_sel) {
    int n = blockIdx.x;
    int t = threadIdx.x;
    int s = g_off[n];
    int e = g_off[n + 1];
    float4 a0 = make_float4(0.f, 0.f, 0.f, 0.f);
    float4 a1 = make_float4(0.f, 0.f, 0.f, 0.f);
    float4 a2 = make_float4(0.f, 0.f, 0.f, 0.f);
    float4 a3 = make_float4(0.f, 0.f, 0.f, 0.f);
    int i = s;
    if (src_sel == 0) {
        const float4* hv = (const float4*)feat;
        int bt = t >> 5;
        int f4 = t & 31;
        int boff = bt * NNODES * 32 + f4;
        for (; i + 7 < e; i += 8) {
            int s0 = g_esrc_sorted[i];
            int s1 = g_esrc_sorted[i + 1];
            int s2 = g_esrc_sorted[i + 2];
            int s3 = g_esrc_sorted[i + 3];
            int s4 = g_esrc_sorted[i + 4];
            int s5 = g_esrc_sorted[i + 5];
            int s6 = g_esrc_sorted[i + 6];
            int s7 = g_esrc_sorted[i + 7];
            float4 v0 = hv[boff + s0 * 32];
            float4 v1 = hv[boff + s1 * 32];
            float4 v2 = hv[boff + s2 * 32];
            float4 v3 = hv[boff + s3 * 32];
            float4 v4 = hv[boff + s4 * 32];
            float4 v5 = hv[boff + s5 * 32];
            float4 v6 = hv[boff + s6 * 32];
            float4 v7 = hv[boff + s7 * 32];
            a0.x += v0.x; a0.y += v0.y; a0.z += v0.z; a0.w += v0.w;
            a1.x += v1.x; a1.y += v1.y; a1.z += v1.z; a1.w += v1.w;
            a2.x += v2.x; a2.y += v2.y; a2.z += v2.z; a2.w += v2.w;
            a3.x += v3.x; a3.y += v3.y; a3.z += v3.z; a3.w += v3.w;
            a0.x += v4.x; a0.y += v4.y; a0.z += v4.z; a0.w += v4.w;
            a1.x += v5.x; a1.y += v5.y; a1.z += v5.z; a1.w += v5.w;
            a2.x += v6.x; a2.y += v6.y; a2.z += v6.z; a2.w += v6.w;
            a3.x += v7.x; a3.y += v7.y; a3.z += v7.z; a3.w += v7.w;
        }
        for (; i + 3 < e; i += 4) {
            int s0 = g_esrc_sorted[i];
            int s1 = g_esrc_sorted[i + 1];
            int s2 = g_esrc_sorted[i + 2];
            int s3 = g_esrc_sorted[i + 3];
            float4 v0 = hv[boff + s0 * 32];
            float4 v1 = hv[boff + s1 * 32];
            float4 v2 = hv[boff + s2 * 32];
            float4 v3 = hv[boff + s3 * 32];
            a0.x += v0.x; a0.y += v0.y; a0.z += v0.z; a0.w += v0.w;
            a1.x += v1.x; a1.y += v1.y; a1.z += v1.z; a1.w += v1.w;
            a2.x += v2.x; a2.y += v2.y; a2.z += v2.z; a2.w += v2.w;
            a3.x += v3.x; a3.y += v3.y; a3.z += v3.z; a3.w += v3.w;
        }
        for (; i < e; i++) {
            int s0 = g_esrc_sorted[i];
            float4 v0 = hv[boff + s0 * 32];
            a0.x += v0.x; a0.y += v0.y; a0.z += v0.z; a0.w += v0.w;
        }
    } else {
        const float4* hv = (const float4*)g_hB;
        for (; i + 7 < e; i += 8) {
            int s0 = g_esrc_sorted[i];
            int s1 = g_esrc_sorted[i + 1];
            int s2 = g_esrc_sorted[i + 2];
            int s3 = g_esrc_sorted[i + 3];
            int s4 = g_esrc_sorted[i + 4];
            int s5 = g_esrc_sorted[i + 5];
            int s6 = g_esrc_sorted[i + 6];
            int s7 = g_esrc_sorted[i + 7];
            float4 v0 = hv[s0 * 128 + t];
            float4 v1 = hv[s1 * 128 + t];
            float4 v2 = hv[s2 * 128 + t];
            float4 v3 = hv[s3 * 128 + t];
            float4 v4 = hv[s4 * 128 + t];
            float4 v5 = hv[s5 * 128 + t];
            float4 v6 = hv[s6 * 128 + t];
            float4 v7 = hv[s7 * 128 + t];
            a0.x += v0.x; a0.y += v0.y; a0.z += v0.z; a0.w += v0.w;
            a1.x += v1.x; a1.y += v1.y; a1.z += v1.z; a1.w += v1.w;
            a2.x += v2.x; a2.y += v2.y; a2.z += v2.z; a2.w += v2.w;
            a3.x += v3.x; a3.y += v3.y; a3.z += v3.z; a3.w += v3.w;
            a0.x += v4.x; a0.y += v4.y; a0.z += v4.z; a0.w += v4.w;
            a1.x += v5.x; a1.y += v5.y; a1.z += v5.z; a1.w += v5.w;
            a2.x += v6.x; a2.y += v6.y; a2.z += v6.z; a2.w += v6.w;
            a3.x += v7.x; a3.y += v7.y; a3.z += v7.z; a3.w += v7.w;
        }
        for (; i + 3 < e; i += 4) {
            int s0 = g_esrc_sorted[i];
            int s1 = g_esrc_sorted[i + 1];
            int s2 = g_esrc_sorted[i + 2];
            int s3 = g_esrc_sorted[i + 3];
            float4 v0 = hv[s0 * 128 + t];
            float4 v1 = hv[s1 * 128 + t];
            float4 v2 = hv[s2 * 128 + t];
            float4 v3 = hv[s3 * 128 + t];
            a0.x += v0.x; a0.y += v0.y; a0.z += v0.z; a0.w += v0.w;
            a1.x += v1.x; a1.y += v1.y; a1.z += v1.z; a1.w += v1.w;
            a2.x += v2.x; a2.y += v2.y; a2.z += v2.z; a2.w += v2.w;
            a3.x += v3.x; a3.y += v3.y; a3.z += v3.z; a3.w += v3.w;
        }
        for (; i < e; i++) {
            int s0 = g_esrc_sorted[i];
            float4 v0 = hv[s0 * 128 + t];
            a0.x += v0.x; a0.y += v0.y; a0.z += v0.z; a0.w += v0.w;
        }
    }
    float inv = g_invdeg[n];
    float4 r;
    r.x = (a0.x + a1.x + a2.x + a3.x) * inv;
    r.y = (a0.y + a1.y + a2.y + a3.y) * inv;
    r.z = (a0.z + a1.z + a2.z + a3.z) * inv;
    r.w = (a0.w + a1.w + a2.w + a3.w) * inv;
    ((float4*)g_agg)[n * 128 + t] = r;
}

// ---------------- persistent mma.sync bf16x2-split GEMM (ldmatrix) -------
// out[m][n] = sum_k X[m][k]*W[k][n] + b[n]; M=40000, K=256, N=128.
__global__ void __launch_bounds__(256) gemm_mma(const float* __restrict__ feat,
                                                int layer,
                                                const float* __restrict__ bias,
                                                float* __restrict__ out_ext) {
    extern __shared__ uint32_t sm[];
    __shared__ int s_tile;
    uint32_t* Bhi = sm + B_HI_OFF;
    uint32_t* Blo = sm + B_LO_OFF;
    float* sbias = (float*)(sm + BIAS_OFF);

    int tid = threadIdx.x;
    int lane = tid & 31;
    int warp = tid >> 5;
    int g = lane >> 2;
    int t = lane & 3;
    int wr = (warp & 3) * 32;
    int wc = (warp >> 2) * 64;
    uint32_t smbase = smem_u32(sm);

    // ldmatrix lane address components (word offsets)
    int am = lane >> 3;
    int ar = lane & 7;
    int a_base = (wr + ((am & 1) << 3) + ar) * AKS + ((am >> 1) << 2);
    int b_base = (wc + ((lane >> 4) << 3) + ar) * BKS + (((lane >> 3) & 1) << 2);

    if (tid < 128) sbias[tid] = bias[tid];

    // stage B once: straight uint4 copy of pre-split planes
    const uint4* bhv = (const uint4*)(g_WThi + layer * 128 * 128);
    const uint4* blv = (const uint4*)(g_WTlo + layer * 128 * 128);
#pragma unroll
    for (int i = 0; i < 16; i++) {
        int lin = tid + i * 256;
        int n = lin >> 5;
        int j = lin & 31;
        *(uint4*)&Bhi[n * BKS + 4 * j] = bhv[lin];
        *(uint4*)&Blo[n * BKS + 4 * j] = blv[lin];
    }

    const float4* x0v = (layer == 0) ? (const float4*)feat : (const float4*)g_hB;
    const float4* x1v = (const float4*)g_agg;

    while (true) {
        if (tid == 0) s_tile = atomicAdd(&g_tilectr[layer], 1);
        __syncthreads();
        int tnum = s_tile;
        if (tnum >= NTILES) break;
        int tile = tnum * 128;

        float acc[2][8][4];
#pragma unroll
        for (int rb = 0; rb < 2; rb++)
#pragma unroll
            for (int nb = 0; nb < 8; nb++)
#pragma unroll
                for (int c = 0; c < 4; c++) acc[rb][nb][c] = 0.f;

        // preload chunk 0 (8 float4 per thread)
        float4 v[8];
#pragma unroll
        for (int i = 0; i < 8; i++) {
            int lin = tid + i * 256;
            int row = lin >> 4;
            int j = lin & 15;
            int m = tile + row;
            if (m >= MROWS) m = MROWS - 1;
            if (layer == 0) {
                int node = m >> 2;
                int bt = m & 3;
                v[i] = x0v[(bt * NNODES + node) * 32 + j];
            } else {
                v[i] = x0v[m * 32 + j];
            }
        }

        for (int kc = 0; kc < 4; kc++) {
            int buf = kc & 1;
            uint32_t* Ahi = sm + A_HI_OFF + buf * ABUF;
            uint32_t* Alo = sm + A_LO_OFF + buf * ABUF;
#pragma unroll
            for (int i = 0; i < 8; i++) {
                int lin = tid + i * 256;
                int row = lin >> 4;
                int j = lin & 15;
                uint32_t h0, l0, h1, l1;
                split2(v[i].x, v[i].y, h0, l0);
                split2(v[i].z, v[i].w, h1, l1);
                *(uint2*)&Ahi[row * AKS + 2 * j] = make_uint2(h0, h1);
                *(uint2*)&Alo[row * AKS + 2 * j] = make_uint2(l0, l1);
            }
            __syncthreads();

            if (kc < 3) {
#pragma unroll
                for (int i = 0; i < 8; i++) {
                    int lin = tid + i * 256;
                    int row = lin >> 4;
                    int j = lin & 15;
                    int m = tile + row;
                    if (m >= MROWS) m = MROWS - 1;
                    int j4 = (kc + 1) * 16 + j;
                    if (j4 < 32) {
                        if (layer == 0) {
                            int node = m >> 2;
                            int bt = m & 3;
                            v[i] = x0v[(bt * NNODES + node) * 32 + j4];
                        } else {
                            v[i] = x0v[m * 32 + j4];
                        }
                    } else {
                        v[i] = x1v[m * 32 + (j4 - 32)];
                    }
                }
            }

            uint32_t ahi_addr = smbase + 4u * (A_HI_OFF + buf * ABUF + a_base);
            uint32_t alo_addr = smbase + 4u * (A_LO_OFF + buf * ABUF + a_base);
#pragma unroll
            for (int ks = 0; ks < 4; ks++) {
                int kb = ks * 8;
                int gb = kc * 32 + kb;
                uint32_t ah[2][4], al[2][4];
#pragma unroll
                for (int rb = 0; rb < 2; rb++) {
                    uint32_t off = 4u * (rb * 16 * AKS + kb);
                    ldsm4(ah[rb][0], ah[rb][1], ah[rb][2], ah[rb][3], ahi_addr + off);
                    ldsm4(al[rb][0], al[rb][1], al[rb][2], al[rb][3], alo_addr + off);
                }
#pragma unroll
                for (int nb = 0; nb < 8; nb += 2) {
                    uint32_t bw = smbase + 4u * (b_base + nb * 8 * BKS + gb);
                    uint32_t bh[4], bl[4];
                    ldsm4(bh[0], bh[1], bh[2], bh[3], bw + 4u * B_HI_OFF);
                    ldsm4(bl[0], bl[1], bl[2], bl[3], bw + 4u * B_LO_OFF);
#pragma unroll
                    for (int rb = 0; rb < 2; rb++) {
                        mma_bf16(acc[rb][nb], ah[rb], bh[0], bh[1]);
                        mma_bf16(acc[rb][nb], al[rb], bh[0], bh[1]);
                        mma_bf16(acc[rb][nb], ah[rb], bl[0], bl[1]);
                        mma_bf16(acc[rb][nb + 1], ah[rb], bh[2], bh[3]);
                        mma_bf16(acc[rb][nb + 1], al[rb], bh[2], bh[3]);
                        mma_bf16(acc[rb][nb + 1], ah[rb], bl[2], bl[3]);
                    }
                }
            }
        }

        // epilogue
#pragma unroll
        for (int rb = 0; rb < 2; rb++) {
#pragma unroll
            for (int h = 0; h < 2; h++) {
                int m = tile + wr + rb * 16 + g + h * 8;
                if (m < MROWS) {
                    float* op;
                    if (layer == 0) {
                        op = g_hB + (size_t)m * 128;
                    } else {
                        int n = m >> 2;
                        int bt = m & 3;
                        op = out_ext + ((size_t)bt * NNODES + n) * 128;
                    }
#pragma unroll
                    for (int nb = 0; nb < 8; nb++) {
                        int col = wc + nb * 8 + 2 * t;
                        float2 vv;
                        vv.x = acc[rb][nb][h * 2 + 0] + sbias[col];
                        vv.y = acc[rb][nb][h * 2 + 1] + sbias[col + 1];
                        *(float2*)(op + col) = vv;
                    }
                }
            }
        }
        __syncthreads();   // protect s_tile / A buffers before next claim
    }
}

// ---------------- launch ----------------
extern "C" void kernel_launch(void* const* d_in, const int* in_sizes, int n_in,
                              void* d_out, int out_size) {
    const float* feat   = (const float*)d_in[0];
    const float* Wself  = (const float*)d_in[1];
    const float* Wneigh = (const float*)d_in[2];
    const float* bias   = (const float*)d_in[3];
    const int*   esrc   = (const int*)d_in[4];
    const int*   edst   = (const int*)d_in[5];
    int E = in_sizes[4];

    cudaFuncSetAttribute(gemm_mma, cudaFuncAttributeMaxDynamicSharedMemorySize,
                         GSMEM_BYTES);

    void *p_deg, *p_cur, *p_ctr, *p_sync;
    cudaGetSymbolAddress(&p_deg, g_deg);
    cudaGetSymbolAddress(&p_cur, g_cursor);
    cudaGetSymbolAddress(&p_ctr, g_tilectr);
    cudaGetSymbolAddress(&p_sync, g_sync);
    cudaMemsetAsync(p_deg, 0, NNODES * sizeof(int));
    cudaMemsetAsync(p_cur, 0, NNODES * sizeof(int));
    cudaMemsetAsync(p_ctr, 0, 2 * sizeof(int));
    cudaMemsetAsync(p_sync, 0, 2 * sizeof(int));

    // kernel order: wt(1), csr(2), agg0(3), gemm0(4) <- ncu captures #4
    wt_kernel<<<(2 * 128 * 128 + 255) / 256, 256>>>(Wself, Wneigh);
    csr_kernel<<<148, 1024>>>(esrc, edst, E);

    // layer 0: agg(feat) -> g_agg, gemm(feat, agg) -> g_hB
    agg_kernel<<<NNODES, 128>>>(feat, 0);
    gemm_mma<<<148, 256, GSMEM_BYTES>>>(feat, 0, bias, (float*)d_out);

    // layer 1: agg(g_hB) -> g_agg, gemm(g_hB, agg) -> d_out ([B,T,N,F])
    agg_kernel<<<NNODES, 128>>>(feat, 1);
    gemm_mma<<<148, 256, GSMEM_BYTES>>>(feat, 1, bias + 128, (float*)d_out);
}

// round 13
// speedup vs baseline: 1.1164x; 1.0165x over previous
#include <cuda_runtime.h>
#include <cuda_bf16.h>
#include <cstdint>

// Problem constants (fixed shapes for this problem instance)
#define NNODES 10000
#define BT 4            // B*T
#define FDIM 128
#define ROW (BT*FDIM)   // 512 floats per node row
#define EMAX 262144
#define MROWS (NNODES*BT)   // 40000 GEMM rows
#define NTILES ((MROWS + 127) / 128)   // 313

// GEMM smem layout (32-bit word offsets into dynamic smem)
#define BKS 132                 // B plane row stride in words (128 kpairs + 4 pad)
#define AKS 36                  // A plane row stride in words (32 kpairs + 4 pad)
#define ABUF (128*AKS)          // 4608 words per A buffer
#define B_HI_OFF 0
#define B_LO_OFF (128*BKS)              // 16896
#define A_HI_OFF (2*128*BKS)            // 33792 (2 buffers)
#define A_LO_OFF (A_HI_OFF + 2*ABUF)    // 43008 (2 buffers)
#define BIAS_OFF (A_LO_OFF + 2*ABUF)    // 52224
#define GSMEM_WORDS (BIAS_OFF + 128)    // 52352
#define GSMEM_BYTES (GSMEM_WORDS*4)     // 209408

// ---------------- device scratch (no allocation allowed) ----------------
__device__ float g_hB[NNODES*ROW];
__device__ float g_agg[NNODES*ROW];
__device__ uint32_t g_WThi[2*128*128];  // per layer: [n][kpair] bf16x2 hi plane
__device__ uint32_t g_WTlo[2*128*128];  // per layer: [n][kpair] bf16x2 lo plane
__device__ int   g_deg[NNODES];
__device__ int   g_cursor[NNODES];
__device__ int   g_off[NNODES+1];
__device__ float g_invdeg[NNODES];
__device__ int   g_esrc_sorted[EMAX];
__device__ int   g_tilectr[2];
__device__ int   g_sync[2];

// ---------------- helpers ----------------
__device__ __forceinline__ uint32_t smem_u32(const void* p) {
    uint32_t a;
    asm("{ .reg .u64 t; cvta.to.shared.u64 t, %1; cvt.u32.u64 %0, t; }"
        : "=r"(a) : "l"(p));
    return a;
}

__device__ __forceinline__ void split2(float a, float b, uint32_t& hi, uint32_t& lo) {
    __nv_bfloat16 ha = __float2bfloat16_rn(a);
    __nv_bfloat16 hb = __float2bfloat16_rn(b);
    float ra = a - __bfloat162float(ha);
    float rb = b - __bfloat162float(hb);
    __nv_bfloat16 la = __float2bfloat16_rn(ra);
    __nv_bfloat16 lb = __float2bfloat16_rn(rb);
    hi = ((uint32_t)__bfloat16_as_ushort(hb) << 16) | (uint32_t)__bfloat16_as_ushort(ha);
    lo = ((uint32_t)__bfloat16_as_ushort(lb) << 16) | (uint32_t)__bfloat16_as_ushort(la);
}

__device__ __forceinline__ void mma_bf16(float* c, const uint32_t* a,
                                         uint32_t b0, uint32_t b1) {
    asm volatile(
        "mma.sync.aligned.m16n8k16.row.col.f32.bf16.bf16.f32 "
        "{%0,%1,%2,%3}, {%4,%5,%6,%7}, {%8,%9}, {%0,%1,%2,%3};"
        : "+f"(c[0]), "+f"(c[1]), "+f"(c[2]), "+f"(c[3])
        : "r"(a[0]), "r"(a[1]), "r"(a[2]), "r"(a[3]), "r"(b0), "r"(b1));
}

__device__ __forceinline__ void ldsm4(uint32_t& r0, uint32_t& r1,
                                      uint32_t& r2, uint32_t& r3, uint32_t addr) {
    asm volatile("ldmatrix.sync.aligned.m8n8.x4.shared.b16 {%0,%1,%2,%3}, [%4];"
                 : "=r"(r0), "=r"(r1), "=r"(r2), "=r"(r3) : "r"(addr));
}

// ---------------- setup kernels ----------------
// #1: weight pre-split (independent of edges)
__global__ void wt_kernel(const float* __restrict__ Wself,
                          const float* __restrict__ Wneigh) {
    int idx = blockIdx.x * blockDim.x + threadIdx.x;   // 2*128*128 = 32768 kpairs
    if (idx >= 2 * 128 * 128) return;
    int l = idx >> 14;
    int rem = idx & 16383;
    int n = rem >> 7;
    int kp = rem & 127;
    float w0, w1;
    if (kp < 64) {
        int k = 2 * kp;
        w0 = Wself[l * 16384 + k * 128 + n];
        w1 = Wself[l * 16384 + (k + 1) * 128 + n];
    } else {
        int k = 2 * kp - 128;
        w0 = Wneigh[l * 16384 + k * 128 + n];
        w1 = Wneigh[l * 16384 + (k + 1) * 128 + n];
    }
    uint32_t hi, lo;
    split2(w0, w1, hi, lo);
    g_WThi[idx] = hi;
    g_WTlo[idx] = lo;
}

// #2: fused CSR build: degree -> (grid spin barrier) -> scan (block 0)
//     -> (flag barrier) -> bucket. Grid 148x1024, 1 CTA/SM, all resident.
__global__ void __launch_bounds__(1024) csr_kernel(const int* __restrict__ esrc,
                                                   const int* __restrict__ edst,
                                                   int E) {
    int tid = threadIdx.x;
    int gid = blockIdx.x * 1024 + tid;
    int nthreads = gridDim.x * 1024;
    int n4 = E >> 2;

    // --- phase 1: degree histogram (int4) ---
    for (int j = gid; j < n4; j += nthreads) {
        int4 v = ((const int4*)edst)[j];
        atomicAdd(&g_deg[v.x], 1);
        atomicAdd(&g_deg[v.y], 1);
        atomicAdd(&g_deg[v.z], 1);
        atomicAdd(&g_deg[v.w], 1);
    }
    if (gid == 0) {
        for (int e = n4 * 4; e < E; e++) atomicAdd(&g_deg[edst[e]], 1);
    }
    __threadfence();
    __syncthreads();
    if (tid == 0) {
        atomicAdd(&g_sync[0], 1);
        while (atomicAdd(&g_sync[0], 0) < (int)gridDim.x) __nanosleep(64);
    }
    __syncthreads();

    // --- phase 2: exclusive scan + inv_deg (block 0 only, 1024 threads) ---
    if (blockIdx.x == 0) {
        __shared__ int wsum[32];
        int lane = tid & 31;
        int w = tid >> 5;
        int base = tid * 10;
        int d[10];
        int tot = 0;
#pragma unroll
        for (int j = 0; j < 10; j++) {
            int idx = base + j;
            d[j] = (idx < NNODES) ? g_deg[idx] : 0;
            tot += d[j];
        }
        int inc = tot;
#pragma unroll
        for (int off = 1; off < 32; off <<= 1) {
            int nv = __shfl_up_sync(0xffffffffu, inc, off);
            if (lane >= off) inc += nv;
        }
        if (lane == 31) wsum[w] = inc;
        __syncthreads();
        if (w == 0) {
            int v = wsum[lane];
            int i2 = v;
#pragma unroll
            for (int off = 1; off < 32; off <<= 1) {
                int nv = __shfl_up_sync(0xffffffffu, i2, off);
                if (lane >= off) i2 += nv;
            }
            wsum[lane] = i2 - v;
        }
        __syncthreads();
        int run = wsum[w] + inc - tot;
#pragma unroll
        for (int j = 0; j < 10; j++) {
            int idx = base + j;
            if (idx < NNODES) {
                g_off[idx] = run;
                g_invdeg[idx] = (d[j] > 0) ? (1.0f / (float)d[j]) : 0.0f;
            }
            run += d[j];
        }
        if (tid == 0) g_off[NNODES] = E;
        __threadfence();
        __syncthreads();
        if (tid == 0) atomicExch(&g_sync[1], 1);
    }
    if (tid == 0) {
        while (atomicAdd(&g_sync[1], 0) == 0) __nanosleep(64);
    }
    __syncthreads();

    // --- phase 3: bucket scatter ---
    for (int j = gid; j < n4; j += nthreads) {
        int4 s = ((const int4*)esrc)[j];
        int4 d = ((const int4*)edst)[j];
        int p;
        p = g_off[d.x] + atomicAdd(&g_cursor[d.x], 1); g_esrc_sorted[p] = s.x;
        p = g_off[d.y] + atomicAdd(&g_cursor[d.y], 1); g_esrc_sorted[p] = s.y;
        p = g_off[d.z] + atomicAdd(&g_cursor[d.z], 1); g_esrc_sorted[p] = s.z;
        p = g_off[d.w] + atomicAdd(&g_cursor[d.w], 1); g_esrc_sorted[p] = s.w;
    }
    if (gid == 0) {
        for (int e = n4 * 4; e < E; e++) {
            int dn = edst[e];
            int p = g_off[dn] + atomicAdd(&g_cursor[dn], 1);
            g_esrc_sorted[p] = esrc[e];
        }
    }
}

// ---------------- mean aggregation: one CTA per dst node, 8-wide MLP -----
__global__ void __launch_bounds__(128) agg_kernel(const float* __restrict__ feat,
                                                  int src_sel) {
    int n = blockIdx.x;
    int t = threadIdx.x;
    int s = g_off[n];
    int e = g_off[n + 1];
    float4 a0 = make_float4(0.f, 0.f, 0.f, 0.f);
    float4 a1 = make_float4(0.f, 0.f, 0.f, 0.f);
    float4 a2 = make_float4(0.f, 0.f, 0.f, 0.f);
    float4 a3 = make_float4(0.f, 0.f, 0.f, 0.f);
    int i = s;
    if (src_sel == 0) {
        const float4* hv = (const float4*)feat;
        int bt = t >> 5;
        int f4 = t & 31;
        int boff = bt * NNODES * 32 + f4;
        for (; i + 7 < e; i += 8) {
            int s0 = g_esrc_sorted[i];
            int s1 = g_esrc_sorted[i + 1];
            int s2 = g_esrc_sorted[i + 2];
            int s3 = g_esrc_sorted[i + 3];
            int s4 = g_esrc_sorted[i + 4];
            int s5 = g_esrc_sorted[i + 5];
            int s6 = g_esrc_sorted[i + 6];
            int s7 = g_esrc_sorted[i + 7];
            float4 v0 = hv[boff + s0 * 32];
            float4 v1 = hv[boff + s1 * 32];
            float4 v2 = hv[boff + s2 * 32];
            float4 v3 = hv[boff + s3 * 32];
            float4 v4 = hv[boff + s4 * 32];
            float4 v5 = hv[boff + s5 * 32];
            float4 v6 = hv[boff + s6 * 32];
            float4 v7 = hv[boff + s7 * 32];
            a0.x += v0.x; a0.y += v0.y; a0.z += v0.z; a0.w += v0.w;
            a1.x += v1.x; a1.y += v1.y; a1.z += v1.z; a1.w += v1.w;
            a2.x += v2.x; a2.y += v2.y; a2.z += v2.z; a2.w += v2.w;
            a3.x += v3.x; a3.y += v3.y; a3.z += v3.z; a3.w += v3.w;
            a0.x += v4.x; a0.y += v4.y; a0.z += v4.z; a0.w += v4.w;
            a1.x += v5.x; a1.y += v5.y; a1.z += v5.z; a1.w += v5.w;
            a2.x += v6.x; a2.y += v6.y; a2.z += v6.z; a2.w += v6.w;
            a3.x += v7.x; a3.y += v7.y; a3.z += v7.z; a3.w += v7.w;
        }
        for (; i + 3 < e; i += 4) {
            int s0 = g_esrc_sorted[i];
            int s1 = g_esrc_sorted[i + 1];
            int s2 = g_esrc_sorted[i + 2];
            int s3 = g_esrc_sorted[i + 3];
            float4 v0 = hv[boff + s0 * 32];
            float4 v1 = hv[boff + s1 * 32];
            float4 v2 = hv[boff + s2 * 32];
            float4 v3 = hv[boff + s3 * 32];
            a0.x += v0.x; a0.y += v0.y; a0.z += v0.z; a0.w += v0.w;
            a1.x += v1.x; a1.y += v1.y; a1.z += v1.z; a1.w += v1.w;
            a2.x += v2.x; a2.y += v2.y; a2.z += v2.z; a2.w += v2.w;
            a3.x += v3.x; a3.y += v3.y; a3.z += v3.z; a3.w += v3.w;
        }
        for (; i < e; i++) {
            int s0 = g_esrc_sorted[i];
            float4 v0 = hv[boff + s0 * 32];
            a0.x += v0.x; a0.y += v0.y; a0.z += v0.z; a0.w += v0.w;
        }
    } else {
        const float4* hv = (const float4*)g_hB;
        for (; i + 7 < e; i += 8) {
            int s0 = g_esrc_sorted[i];
            int s1 = g_esrc_sorted[i + 1];
            int s2 = g_esrc_sorted[i + 2];
            int s3 = g_esrc_sorted[i + 3];
            int s4 = g_esrc_sorted[i + 4];
            int s5 = g_esrc_sorted[i + 5];
            int s6 = g_esrc_sorted[i + 6];
            int s7 = g_esrc_sorted[i + 7];
            float4 v0 = hv[s0 * 128 + t];
            float4 v1 = hv[s1 * 128 + t];
            float4 v2 = hv[s2 * 128 + t];
            float4 v3 = hv[s3 * 128 + t];
            float4 v4 = hv[s4 * 128 + t];
            float4 v5 = hv[s5 * 128 + t];
            float4 v6 = hv[s6 * 128 + t];
            float4 v7 = hv[s7 * 128 + t];
            a0.x += v0.x; a0.y += v0.y; a0.z += v0.z; a0.w += v0.w;
            a1.x += v1.x; a1.y += v1.y; a1.z += v1.z; a1.w += v1.w;
            a2.x += v2.x; a2.y += v2.y; a2.z += v2.z; a2.w += v2.w;
            a3.x += v3.x; a3.y += v3.y; a3.z += v3.z; a3.w += v3.w;
            a0.x += v4.x; a0.y += v4.y; a0.z += v4.z; a0.w += v4.w;
            a1.x += v5.x; a1.y += v5.y; a1.z += v5.z; a1.w += v5.w;
            a2.x += v6.x; a2.y += v6.y; a2.z += v6.z; a2.w += v6.w;
            a3.x += v7.x; a3.y += v7.y; a3.z += v7.z; a3.w += v7.w;
        }
        for (; i + 3 < e; i += 4) {
            int s0 = g_esrc_sorted[i];
            int s1 = g_esrc_sorted[i + 1];
            int s2 = g_esrc_sorted[i + 2];
            int s3 = g_esrc_sorted[i + 3];
            float4 v0 = hv[s0 * 128 + t];
            float4 v1 = hv[s1 * 128 + t];
            float4 v2 = hv[s2 * 128 + t];
            float4 v3 = hv[s3 * 128 + t];
            a0.x += v0.x; a0.y += v0.y; a0.z += v0.z; a0.w += v0.w;
            a1.x += v1.x; a1.y += v1.y; a1.z += v1.z; a1.w += v1.w;
            a2.x += v2.x; a2.y += v2.y; a2.z += v2.z; a2.w += v2.w;
            a3.x += v3.x; a3.y += v3.y; a3.z += v3.z; a3.w += v3.w;
        }
        for (; i < e; i++) {
            int s0 = g_esrc_sorted[i];
            float4 v0 = hv[s0 * 128 + t];
            a0.x += v0.x; a0.y += v0.y; a0.z += v0.z; a0.w += v0.w;
        }
    }
    float inv = g_invdeg[n];
    float4 r;
    r.x = (a0.x + a1.x + a2.x + a3.x) * inv;
    r.y = (a0.y + a1.y + a2.y + a3.y) * inv;
    r.z = (a0.z + a1.z + a2.z + a3.z) * inv;
    r.w = (a0.w + a1.w + a2.w + a3.w) * inv;
    ((float4*)g_agg)[n * 128 + t] = r;
}

// ---------------- persistent mma.sync bf16x2-split GEMM (512 thr) --------
// out[m][n] = sum_k X[m][k]*W[k][n] + b[n]; M=40000, K=256, N=128.
// 16 warps, warp grid 4x4 (warp tile 32x32) -> 4 warps/SMSP latency hiding.
__global__ void __launch_bounds__(512) gemm_mma(const float* __restrict__ feat,
                                                int layer,
                                                const float* __restrict__ bias,
                                                float* __restrict__ out_ext) {
    extern __shared__ uint32_t sm[];
    __shared__ int s_tile;
    uint32_t* Bhi = sm + B_HI_OFF;
    uint32_t* Blo = sm + B_LO_OFF;
    float* sbias = (float*)(sm + BIAS_OFF);

    int tid = threadIdx.x;
    int lane = tid & 31;
    int warp = tid >> 5;
    int g = lane >> 2;
    int t = lane & 3;
    int wr = (warp & 3) * 32;      // 4 row groups
    int wc = (warp >> 2) * 32;     // 4 col groups
    uint32_t smbase = smem_u32(sm);

    // ldmatrix lane address components (word offsets)
    int am = lane >> 3;
    int ar = lane & 7;
    int a_base = (wr + ((am & 1) << 3) + ar) * AKS + ((am >> 1) << 2);
    int b_base = (wc + ((lane >> 4) << 3) + ar) * BKS + (((lane >> 3) & 1) << 2);

    if (tid < 128) sbias[tid] = bias[tid];

    // stage B once: straight uint4 copy of pre-split planes (4096 uint4/plane)
    const uint4* bhv = (const uint4*)(g_WThi + layer * 128 * 128);
    const uint4* blv = (const uint4*)(g_WTlo + layer * 128 * 128);
#pragma unroll
    for (int i = 0; i < 8; i++) {
        int lin = tid + i * 512;
        int n = lin >> 5;
        int j = lin & 31;
        *(uint4*)&Bhi[n * BKS + 4 * j] = bhv[lin];
        *(uint4*)&Blo[n * BKS + 4 * j] = blv[lin];
    }

    const float4* x0v = (layer == 0) ? (const float4*)feat : (const float4*)g_hB;
    const float4* x1v = (const float4*)g_agg;

    while (true) {
        if (tid == 0) s_tile = atomicAdd(&g_tilectr[layer], 1);
        __syncthreads();
        int tnum = s_tile;
        if (tnum >= NTILES) break;
        int tile = tnum * 128;

        float acc[2][4][4];
#pragma unroll
        for (int rb = 0; rb < 2; rb++)
#pragma unroll
            for (int nb = 0; nb < 4; nb++)
#pragma unroll
                for (int c = 0; c < 4; c++) acc[rb][nb][c] = 0.f;

        // preload chunk 0 (4 float4 per thread; 2048 total = 128 rows x 16)
        float4 v[4];
#pragma unroll
        for (int i = 0; i < 4; i++) {
            int lin = tid + i * 512;
            int row = lin >> 4;
            int j = lin & 15;
            int m = tile + row;
            if (m >= MROWS) m = MROWS - 1;
            if (layer == 0) {
                int node = m >> 2;
                int bt = m & 3;
                v[i] = x0v[(bt * NNODES + node) * 32 + j];
            } else {
                v[i] = x0v[m * 32 + j];
            }
        }

        for (int kc = 0; kc < 4; kc++) {
            int buf = kc & 1;
            uint32_t* Ahi = sm + A_HI_OFF + buf * ABUF;
            uint32_t* Alo = sm + A_LO_OFF + buf * ABUF;
#pragma unroll
            for (int i = 0; i < 4; i++) {
                int lin = tid + i * 512;
                int row = lin >> 4;
                int j = lin & 15;
                uint32_t h0, l0, h1, l1;
                split2(v[i].x, v[i].y, h0, l0);
                split2(v[i].z, v[i].w, h1, l1);
                *(uint2*)&Ahi[row * AKS + 2 * j] = make_uint2(h0, h1);
                *(uint2*)&Alo[row * AKS + 2 * j] = make_uint2(l0, l1);
            }
            __syncthreads();

            if (kc < 3) {
#pragma unroll
                for (int i = 0; i < 4; i++) {
                    int lin = tid + i * 512;
                    int row = lin >> 4;
                    int j = lin & 15;
                    int m = tile + row;
                    if (m >= MROWS) m = MROWS - 1;
                    int j4 = (kc + 1) * 16 + j;
                    if (j4 < 32) {
                        if (layer == 0) {
                            int node = m >> 2;
                            int bt = m & 3;
                            v[i] = x0v[(bt * NNODES + node) * 32 + j4];
                        } else {
                            v[i] = x0v[m * 32 + j4];
                        }
                    } else {
                        v[i] = x1v[m * 32 + (j4 - 32)];
                    }
                }
            }

            uint32_t ahi_addr = smbase + 4u * (A_HI_OFF + buf * ABUF + a_base);
            uint32_t alo_addr = smbase + 4u * (A_LO_OFF + buf * ABUF + a_base);
#pragma unroll
            for (int ks = 0; ks < 4; ks++) {
                int kb = ks * 8;
                int gb = kc * 32 + kb;
                uint32_t ah[2][4], al[2][4];
#pragma unroll
                for (int rb = 0; rb < 2; rb++) {
                    uint32_t off = 4u * (rb * 16 * AKS + kb);
                    ldsm4(ah[rb][0], ah[rb][1], ah[rb][2], ah[rb][3], ahi_addr + off);
                    ldsm4(al[rb][0], al[rb][1], al[rb][2], al[rb][3], alo_addr + off);
                }
#pragma unroll
                for (int nb = 0; nb < 4; nb += 2) {
                    uint32_t bw = smbase + 4u * (b_base + nb * 8 * BKS + gb);
                    uint32_t bh[4], bl[4];
                    ldsm4(bh[0], bh[1], bh[2], bh[3], bw + 4u * B_HI_OFF);
                    ldsm4(bl[0], bl[1], bl[2], bl[3], bw + 4u * B_LO_OFF);
#pragma unroll
                    for (int rb = 0; rb < 2; rb++) {
                        mma_bf16(acc[rb][nb], ah[rb], bh[0], bh[1]);
                        mma_bf16(acc[rb][nb], al[rb], bh[0], bh[1]);
                        mma_bf16(acc[rb][nb], ah[rb], bl[0], bl[1]);
                        mma_bf16(acc[rb][nb + 1], ah[rb], bh[2], bh[3]);
                        mma_bf16(acc[rb][nb + 1], al[rb], bh[2], bh[3]);
                        mma_bf16(acc[rb][nb + 1], ah[rb], bl[2], bl[3]);
                    }
                }
            }
        }

        // epilogue
#pragma unroll
        for (int rb = 0; rb < 2; rb++) {
#pragma unroll
            for (int h = 0; h < 2; h++) {
                int m = tile + wr + rb * 16 + g + h * 8;
                if (m < MROWS) {
                    float* op;
                    if (layer == 0) {
                        op = g_hB + (size_t)m * 128;
                    } else {
                        int n = m >> 2;
                        int bt = m & 3;
                        op = out_ext + ((size_t)bt * NNODES + n) * 128;
                    }
#pragma unroll
                    for (int nb = 0; nb < 4; nb++) {
                        int col = wc + nb * 8 + 2 * t;
                        float2 vv;
                        vv.x = acc[rb][nb][h * 2 + 0] + sbias[col];
                        vv.y = acc[rb][nb][h * 2 + 1] + sbias[col + 1];
                        *(float2*)(op + col) = vv;
                    }
                }
            }
        }
        __syncthreads();   // protect s_tile / A buffers before next claim
    }
}

// ---------------- launch ----------------
extern "C" void kernel_launch(void* const* d_in, const int* in_sizes, int n_in,
                              void* d_out, int out_size) {
    const float* feat   = (const float*)d_in[0];
    const float* Wself  = (const float*)d_in[1];
    const float* Wneigh = (const float*)d_in[2];
    const float* bias   = (const float*)d_in[3];
    const int*   esrc   = (const int*)d_in[4];
    const int*   edst   = (const int*)d_in[5];
    int E = in_sizes[4];

    cudaFuncSetAttribute(gemm_mma, cudaFuncAttributeMaxDynamicSharedMemorySize,
                         GSMEM_BYTES);

    void *p_deg, *p_cur, *p_ctr, *p_sync;
    cudaGetSymbolAddress(&p_deg, g_deg);
    cudaGetSymbolAddress(&p_cur, g_cursor);
    cudaGetSymbolAddress(&p_ctr, g_tilectr);
    cudaGetSymbolAddress(&p_sync, g_sync);
    cudaMemsetAsync(p_deg, 0, NNODES * sizeof(int));
    cudaMemsetAsync(p_cur, 0, NNODES * sizeof(int));
    cudaMemsetAsync(p_ctr, 0, 2 * sizeof(int));
    cudaMemsetAsync(p_sync, 0, 2 * sizeof(int));

    // kernel order: wt(1), csr(2), agg0(3), gemm0(4) <- ncu captures #4
    wt_kernel<<<(2 * 128 * 128 + 255) / 256, 256>>>(Wself, Wneigh);
    csr_kernel<<<148, 1024>>>(esrc, edst, E);

    // layer 0: agg(feat) -> g_agg, gemm(feat, agg) -> g_hB
    agg_kernel<<<NNODES, 128>>>(feat, 0);
    gemm_mma<<<148, 512, GSMEM_BYTES>>>(feat, 0, bias, (float*)d_out);

    // layer 1: agg(g_hB) -> g_agg, gemm(g_hB, agg) -> d_out ([B,T,N,F])
    agg_kernel<<<NNODES, 128>>>(feat, 1);
    gemm_mma<<<148, 512, GSMEM_BYTES>>>(feat, 1, bias + 128, (float*)d_out);
}

// round 14
// speedup vs baseline: 1.1739x; 1.0515x over previous
#include <cuda_runtime.h>
#include <cuda_bf16.h>
#include <cstdint>

// Problem constants (fixed shapes for this problem instance)
#define NNODES 10000
#define BT 4            // B*T
#define FDIM 128
#define ROW (BT*FDIM)   // 512 floats per node row
#define EMAX 262144
#define MROWS (NNODES*BT)   // 40000 GEMM rows
#define TILE_M 64
#define NTILES ((MROWS + TILE_M - 1) / TILE_M)   // 625

// GEMM smem layout (32-bit word offsets into dynamic smem)
#define BKS 132                 // B plane row stride in words (128 kpairs + 4 pad)
#define AKS 36                  // A plane row stride in words (32 kpairs + 4 pad)
#define ABUF (TILE_M*AKS)       // 2304 words per A buffer
#define B_HI_OFF 0
#define B_LO_OFF (128*BKS)              // 16896
#define A_HI_OFF (2*128*BKS)            // 33792 (2 buffers)
#define A_LO_OFF (A_HI_OFF + 2*ABUF)    // 38400 (2 buffers)
#define BIAS_OFF (A_LO_OFF + 2*ABUF)    // 43008
#define GSMEM_WORDS (BIAS_OFF + 128)    // 43136
#define GSMEM_BYTES (GSMEM_WORDS*4)     // 172544

// ---------------- device scratch (no allocation allowed) ----------------
__device__ float g_hB[NNODES*ROW];
__device__ float g_agg[NNODES*ROW];
__device__ uint32_t g_WThi[2*128*128];  // per layer: [n][kpair] bf16x2 hi plane
__device__ uint32_t g_WTlo[2*128*128];  // per layer: [n][kpair] bf16x2 lo plane
__device__ int   g_deg[NNODES];
__device__ int   g_cursor[NNODES];
__device__ int   g_off[NNODES+1];
__device__ float g_invdeg[NNODES];
__device__ int   g_esrc_sorted[EMAX];
__device__ int   g_tilectr[2];
__device__ int   g_sync[2];

// ---------------- helpers ----------------
__device__ __forceinline__ uint32_t smem_u32(const void* p) {
    uint32_t a;
    asm("{ .reg .u64 t; cvta.to.shared.u64 t, %1; cvt.u32.u64 %0, t; }"
        : "=r"(a) : "l"(p));
    return a;
}

__device__ __forceinline__ void split2(float a, float b, uint32_t& hi, uint32_t& lo) {
    __nv_bfloat16 ha = __float2bfloat16_rn(a);
    __nv_bfloat16 hb = __float2bfloat16_rn(b);
    float ra = a - __bfloat162float(ha);
    float rb = b - __bfloat162float(hb);
    __nv_bfloat16 la = __float2bfloat16_rn(ra);
    __nv_bfloat16 lb = __float2bfloat16_rn(rb);
    hi = ((uint32_t)__bfloat16_as_ushort(hb) << 16) | (uint32_t)__bfloat16_as_ushort(ha);
    lo = ((uint32_t)__bfloat16_as_ushort(lb) << 16) | (uint32_t)__bfloat16_as_ushort(la);
}

__device__ __forceinline__ void mma_bf16(float* c, const uint32_t* a,
                                         uint32_t b0, uint32_t b1) {
    asm volatile(
        "mma.sync.aligned.m16n8k16.row.col.f32.bf16.bf16.f32 "
        "{%0,%1,%2,%3}, {%4,%5,%6,%7}, {%8,%9}, {%0,%1,%2,%3};"
        : "+f"(c[0]), "+f"(c[1]), "+f"(c[2]), "+f"(c[3])
        : "r"(a[0]), "r"(a[1]), "r"(a[2]), "r"(a[3]), "r"(b0), "r"(b1));
}

__device__ __forceinline__ void ldsm4(uint32_t& r0, uint32_t& r1,
                                      uint32_t& r2, uint32_t& r3, uint32_t addr) {
    asm volatile("ldmatrix.sync.aligned.m8n8.x4.shared.b16 {%0,%1,%2,%3}, [%4];"
                 : "=r"(r0), "=r"(r1), "=r"(r2), "=r"(r3) : "r"(addr));
}

// ---------------- setup kernels ----------------
// #1: weight pre-split (independent of edges)
__global__ void wt_kernel(const float* __restrict__ Wself,
                          const float* __restrict__ Wneigh) {
    int idx = blockIdx.x * blockDim.x + threadIdx.x;   // 2*128*128 = 32768 kpairs
    if (idx >= 2 * 128 * 128) return;
    int l = idx >> 14;
    int rem = idx & 16383;
    int n = rem >> 7;
    int kp = rem & 127;
    float w0, w1;
    if (kp < 64) {
        int k = 2 * kp;
        w0 = Wself[l * 16384 + k * 128 + n];
        w1 = Wself[l * 16384 + (k + 1) * 128 + n];
    } else {
        int k = 2 * kp - 128;
        w0 = Wneigh[l * 16384 + k * 128 + n];
        w1 = Wneigh[l * 16384 + (k + 1) * 128 + n];
    }
    uint32_t hi, lo;
    split2(w0, w1, hi, lo);
    g_WThi[idx] = hi;
    g_WTlo[idx] = lo;
}

// #2: fused CSR build: degree -> (grid spin barrier) -> scan (block 0)
//     -> (flag barrier) -> bucket. Grid 148x1024, 1 CTA/SM, all resident.
__global__ void __launch_bounds__(1024) csr_kernel(const int* __restrict__ esrc,
                                                   const int* __restrict__ edst,
                                                   int E) {
    int tid = threadIdx.x;
    int gid = blockIdx.x * 1024 + tid;
    int nthreads = gridDim.x * 1024;
    int n4 = E >> 2;

    // --- phase 1: degree histogram (int4) ---
    for (int j = gid; j < n4; j += nthreads) {
        int4 v = ((const int4*)edst)[j];
        atomicAdd(&g_deg[v.x], 1);
        atomicAdd(&g_deg[v.y], 1);
        atomicAdd(&g_deg[v.z], 1);
        atomicAdd(&g_deg[v.w], 1);
    }
    if (gid == 0) {
        for (int e = n4 * 4; e < E; e++) atomicAdd(&g_deg[edst[e]], 1);
    }
    __threadfence();
    __syncthreads();
    if (tid == 0) {
        atomicAdd(&g_sync[0], 1);
        while (atomicAdd(&g_sync[0], 0) < (int)gridDim.x) __nanosleep(64);
    }
    __syncthreads();

    // --- phase 2: exclusive scan + inv_deg (block 0 only, 1024 threads) ---
    if (blockIdx.x == 0) {
        __shared__ int wsum[32];
        int lane = tid & 31;
        int w = tid >> 5;
        int base = tid * 10;
        int d[10];
        int tot = 0;
#pragma unroll
        for (int j = 0; j < 10; j++) {
            int idx = base + j;
            d[j] = (idx < NNODES) ? g_deg[idx] : 0;
            tot += d[j];
        }
        int inc = tot;
#pragma unroll
        for (int off = 1; off < 32; off <<= 1) {
            int nv = __shfl_up_sync(0xffffffffu, inc, off);
            if (lane >= off) inc += nv;
        }
        if (lane == 31) wsum[w] = inc;
        __syncthreads();
        if (w == 0) {
            int v = wsum[lane];
            int i2 = v;
#pragma unroll
            for (int off = 1; off < 32; off <<= 1) {
                int nv = __shfl_up_sync(0xffffffffu, i2, off);
                if (lane >= off) i2 += nv;
            }
            wsum[lane] = i2 - v;
        }
        __syncthreads();
        int run = wsum[w] + inc - tot;
#pragma unroll
        for (int j = 0; j < 10; j++) {
            int idx = base + j;
            if (idx < NNODES) {
                g_off[idx] = run;
                g_invdeg[idx] = (d[j] > 0) ? (1.0f / (float)d[j]) : 0.0f;
            }
            run += d[j];
        }
        if (tid == 0) g_off[NNODES] = E;
        __threadfence();
        __syncthreads();
        if (tid == 0) atomicExch(&g_sync[1], 1);
    }
    if (tid == 0) {
        while (atomicAdd(&g_sync[1], 0) == 0) __nanosleep(64);
    }
    __syncthreads();

    // --- phase 3: bucket scatter ---
    for (int j = gid; j < n4; j += nthreads) {
        int4 s = ((const int4*)esrc)[j];
        int4 d = ((const int4*)edst)[j];
        int p;
        p = g_off[d.x] + atomicAdd(&g_cursor[d.x], 1); g_esrc_sorted[p] = s.x;
        p = g_off[d.y] + atomicAdd(&g_cursor[d.y], 1); g_esrc_sorted[p] = s.y;
        p = g_off[d.z] + atomicAdd(&g_cursor[d.z], 1); g_esrc_sorted[p] = s.z;
        p = g_off[d.w] + atomicAdd(&g_cursor[d.w], 1); g_esrc_sorted[p] = s.w;
    }
    if (gid == 0) {
        for (int e = n4 * 4; e < E; e++) {
            int dn = edst[e];
            int p = g_off[dn] + atomicAdd(&g_cursor[dn], 1);
            g_esrc_sorted[p] = esrc[e];
        }
    }
}

// ---------------- mean aggregation: one CTA per dst node, 8-wide MLP -----
__global__ void __launch_bounds__(128) agg_kernel(const float* __restrict__ feat,
                                                  int src_sel) {
    int n = blockIdx.x;
    int t = threadIdx.x;
    int s = g_off[n];
    int e = g_off[n + 1];
    float4 a0 = make_float4(0.f, 0.f, 0.f, 0.f);
    float4 a1 = make_float4(0.f, 0.f, 0.f, 0.f);
    float4 a2 = make_float4(0.f, 0.f, 0.f, 0.f);
    float4 a3 = make_float4(0.f, 0.f, 0.f, 0.f);
    int i = s;
    if (src_sel == 0) {
        const float4* hv = (const float4*)feat;
        int bt = t >> 5;
        int f4 = t & 31;
        int boff = bt * NNODES * 32 + f4;
        for (; i + 7 < e; i += 8) {
            int s0 = g_esrc_sorted[i];
            int s1 = g_esrc_sorted[i + 1];
            int s2 = g_esrc_sorted[i + 2];
            int s3 = g_esrc_sorted[i + 3];
            int s4 = g_esrc_sorted[i + 4];
            int s5 = g_esrc_sorted[i + 5];
            int s6 = g_esrc_sorted[i + 6];
            int s7 = g_esrc_sorted[i + 7];
            float4 v0 = hv[boff + s0 * 32];
            float4 v1 = hv[boff + s1 * 32];
            float4 v2 = hv[boff + s2 * 32];
            float4 v3 = hv[boff + s3 * 32];
            float4 v4 = hv[boff + s4 * 32];
            float4 v5 = hv[boff + s5 * 32];
            float4 v6 = hv[boff + s6 * 32];
            float4 v7 = hv[boff + s7 * 32];
            a0.x += v0.x; a0.y += v0.y; a0.z += v0.z; a0.w += v0.w;
            a1.x += v1.x; a1.y += v1.y; a1.z += v1.z; a1.w += v1.w;
            a2.x += v2.x; a2.y += v2.y; a2.z += v2.z; a2.w += v2.w;
            a3.x += v3.x; a3.y += v3.y; a3.z += v3.z; a3.w += v3.w;
            a0.x += v4.x; a0.y += v4.y; a0.z += v4.z; a0.w += v4.w;
            a1.x += v5.x; a1.y += v5.y; a1.z += v5.z; a1.w += v5.w;
            a2.x += v6.x; a2.y += v6.y; a2.z += v6.z; a2.w += v6.w;
            a3.x += v7.x; a3.y += v7.y; a3.z += v7.z; a3.w += v7.w;
        }
        for (; i + 3 < e; i += 4) {
            int s0 = g_esrc_sorted[i];
            int s1 = g_esrc_sorted[i + 1];
            int s2 = g_esrc_sorted[i + 2];
            int s3 = g_esrc_sorted[i + 3];
            float4 v0 = hv[boff + s0 * 32];
            float4 v1 = hv[boff + s1 * 32];
            float4 v2 = hv[boff + s2 * 32];
            float4 v3 = hv[boff + s3 * 32];
            a0.x += v0.x; a0.y += v0.y; a0.z += v0.z; a0.w += v0.w;
            a1.x += v1.x; a1.y += v1.y; a1.z += v1.z; a1.w += v1.w;
            a2.x += v2.x; a2.y += v2.y; a2.z += v2.z; a2.w += v2.w;
            a3.x += v3.x; a3.y += v3.y; a3.z += v3.z; a3.w += v3.w;
        }
        for (; i < e; i++) {
            int s0 = g_esrc_sorted[i];
            float4 v0 = hv[boff + s0 * 32];
            a0.x += v0.x; a0.y += v0.y; a0.z += v0.z; a0.w += v0.w;
        }
    } else {
        const float4* hv = (const float4*)g_hB;
        for (; i + 7 < e; i += 8) {
            int s0 = g_esrc_sorted[i];
            int s1 = g_esrc_sorted[i + 1];
            int s2 = g_esrc_sorted[i + 2];
            int s3 = g_esrc_sorted[i + 3];
            int s4 = g_esrc_sorted[i + 4];
            int s5 = g_esrc_sorted[i + 5];
            int s6 = g_esrc_sorted[i + 6];
            int s7 = g_esrc_sorted[i + 7];
            float4 v0 = hv[s0 * 128 + t];
            float4 v1 = hv[s1 * 128 + t];
            float4 v2 = hv[s2 * 128 + t];
            float4 v3 = hv[s3 * 128 + t];
            float4 v4 = hv[s4 * 128 + t];
            float4 v5 = hv[s5 * 128 + t];
            float4 v6 = hv[s6 * 128 + t];
            float4 v7 = hv[s7 * 128 + t];
            a0.x += v0.x; a0.y += v0.y; a0.z += v0.z; a0.w += v0.w;
            a1.x += v1.x; a1.y += v1.y; a1.z += v1.z; a1.w += v1.w;
            a2.x += v2.x; a2.y += v2.y; a2.z += v2.z; a2.w += v2.w;
            a3.x += v3.x; a3.y += v3.y; a3.z += v3.z; a3.w += v3.w;
            a0.x += v4.x; a0.y += v4.y; a0.z += v4.z; a0.w += v4.w;
            a1.x += v5.x; a1.y += v5.y; a1.z += v5.z; a1.w += v5.w;
            a2.x += v6.x; a2.y += v6.y; a2.z += v6.z; a2.w += v6.w;
            a3.x += v7.x; a3.y += v7.y; a3.z += v7.z; a3.w += v7.w;
        }
        for (; i + 3 < e; i += 4) {
            int s0 = g_esrc_sorted[i];
            int s1 = g_esrc_sorted[i + 1];
            int s2 = g_esrc_sorted[i + 2];
            int s3 = g_esrc_sorted[i + 3];
            float4 v0 = hv[s0 * 128 + t];
            float4 v1 = hv[s1 * 128 + t];
            float4 v2 = hv[s2 * 128 + t];
            float4 v3 = hv[s3 * 128 + t];
            a0.x += v0.x; a0.y += v0.y; a0.z += v0.z; a0.w += v0.w;
            a1.x += v1.x; a1.y += v1.y; a1.z += v1.z; a1.w += v1.w;
            a2.x += v2.x; a2.y += v2.y; a2.z += v2.z; a2.w += v2.w;
            a3.x += v3.x; a3.y += v3.y; a3.z += v3.z; a3.w += v3.w;
        }
        for (; i < e; i++) {
            int s0 = g_esrc_sorted[i];
            float4 v0 = hv[s0 * 128 + t];
            a0.x += v0.x; a0.y += v0.y; a0.z += v0.z; a0.w += v0.w;
        }
    }
    float inv = g_invdeg[n];
    float4 r;
    r.x = (a0.x + a1.x + a2.x + a3.x) * inv;
    r.y = (a0.y + a1.y + a2.y + a3.y) * inv;
    r.z = (a0.z + a1.z + a2.z + a3.z) * inv;
    r.w = (a0.w + a1.w + a2.w + a3.w) * inv;
    ((float4*)g_agg)[n * 128 + t] = r;
}

// ---------------- persistent mma.sync bf16x2-split GEMM ------------------
// out[m][n] = sum_k X[m][k]*W[k][n] + b[n]; M=40000, K=256, N=128.
// 64x128 tiles (625) for low work-steal tail; 16 warps, warp tile 16x32.
__global__ void __launch_bounds__(512) gemm_mma(const float* __restrict__ feat,
                                                int layer,
                                                const float* __restrict__ bias,
                                                float* __restrict__ out_ext) {
    extern __shared__ uint32_t sm[];
    __shared__ int s_tile;
    uint32_t* Bhi = sm + B_HI_OFF;
    uint32_t* Blo = sm + B_LO_OFF;
    float* sbias = (float*)(sm + BIAS_OFF);

    int tid = threadIdx.x;
    int lane = tid & 31;
    int warp = tid >> 5;
    int g = lane >> 2;
    int t = lane & 3;
    int wr = (warp & 3) * 16;      // 4 row groups of 16
    int wc = (warp >> 2) * 32;     // 4 col groups of 32
    uint32_t smbase = smem_u32(sm);

    // ldmatrix lane address components (word offsets)
    int am = lane >> 3;
    int ar = lane & 7;
    int a_base = (wr + ((am & 1) << 3) + ar) * AKS + ((am >> 1) << 2);
    int b_base = (wc + ((lane >> 4) << 3) + ar) * BKS + (((lane >> 3) & 1) << 2);

    if (tid < 128) sbias[tid] = bias[tid];

    // stage B once: straight uint4 copy of pre-split planes (4096 uint4/plane)
    const uint4* bhv = (const uint4*)(g_WThi + layer * 128 * 128);
    const uint4* blv = (const uint4*)(g_WTlo + layer * 128 * 128);
#pragma unroll
    for (int i = 0; i < 8; i++) {
        int lin = tid + i * 512;
        int n = lin >> 5;
        int j = lin & 31;
        *(uint4*)&Bhi[n * BKS + 4 * j] = bhv[lin];
        *(uint4*)&Blo[n * BKS + 4 * j] = blv[lin];
    }

    const float4* x0v = (layer == 0) ? (const float4*)feat : (const float4*)g_hB;
    const float4* x1v = (const float4*)g_agg;

    while (true) {
        if (tid == 0) s_tile = atomicAdd(&g_tilectr[layer], 1);
        __syncthreads();
        int tnum = s_tile;
        if (tnum >= NTILES) break;
        int tile = tnum * TILE_M;

        float acc[4][4];
#pragma unroll
        for (int nb = 0; nb < 4; nb++)
#pragma unroll
            for (int c = 0; c < 4; c++) acc[nb][c] = 0.f;

        // preload chunk 0 (2 float4 per thread; 1024 total = 64 rows x 16)
        float4 v[2];
#pragma unroll
        for (int i = 0; i < 2; i++) {
            int lin = tid + i * 512;
            int row = lin >> 4;
            int j = lin & 15;
            int m = tile + row;
            if (m >= MROWS) m = MROWS - 1;
            if (layer == 0) {
                int node = m >> 2;
                int bt = m & 3;
                v[i] = x0v[(bt * NNODES + node) * 32 + j];
            } else {
                v[i] = x0v[m * 32 + j];
            }
        }

        for (int kc = 0; kc < 4; kc++) {
            int buf = kc & 1;
            uint32_t* Ahi = sm + A_HI_OFF + buf * ABUF;
            uint32_t* Alo = sm + A_LO_OFF + buf * ABUF;
#pragma unroll
            for (int i = 0; i < 2; i++) {
                int lin = tid + i * 512;
                int row = lin >> 4;
                int j = lin & 15;
                uint32_t h0, l0, h1, l1;
                split2(v[i].x, v[i].y, h0, l0);
                split2(v[i].z, v[i].w, h1, l1);
                *(uint2*)&Ahi[row * AKS + 2 * j] = make_uint2(h0, h1);
                *(uint2*)&Alo[row * AKS + 2 * j] = make_uint2(l0, l1);
            }
            __syncthreads();

            if (kc < 3) {
#pragma unroll
                for (int i = 0; i < 2; i++) {
                    int lin = tid + i * 512;
                    int row = lin >> 4;
                    int j = lin & 15;
                    int m = tile + row;
                    if (m >= MROWS) m = MROWS - 1;
                    int j4 = (kc + 1) * 16 + j;
                    if (j4 < 32) {
                        if (layer == 0) {
                            int node = m >> 2;
                            int bt = m & 3;
                            v[i] = x0v[(bt * NNODES + node) * 32 + j4];
                        } else {
                            v[i] = x0v[m * 32 + j4];
                        }
                    } else {
                        v[i] = x1v[m * 32 + (j4 - 32)];
                    }
                }
            }

            uint32_t ahi_addr = smbase + 4u * (A_HI_OFF + buf * ABUF + a_base);
            uint32_t alo_addr = smbase + 4u * (A_LO_OFF + buf * ABUF + a_base);
#pragma unroll
            for (int ks = 0; ks < 4; ks++) {
                int kb = ks * 8;
                int gb = kc * 32 + kb;
                uint32_t ah[4], al[4];
                {
                    uint32_t off = 4u * kb;
                    ldsm4(ah[0], ah[1], ah[2], ah[3], ahi_addr + off);
                    ldsm4(al[0], al[1], al[2], al[3], alo_addr + off);
                }
#pragma unroll
                for (int nb = 0; nb < 4; nb += 2) {
                    uint32_t bw = smbase + 4u * (b_base + nb * 8 * BKS + gb);
                    uint32_t bh[4], bl[4];
                    ldsm4(bh[0], bh[1], bh[2], bh[3], bw + 4u * B_HI_OFF);
                    ldsm4(bl[0], bl[1], bl[2], bl[3], bw + 4u * B_LO_OFF);
                    mma_bf16(acc[nb], ah, bh[0], bh[1]);
                    mma_bf16(acc[nb], al, bh[0], bh[1]);
                    mma_bf16(acc[nb], ah, bl[0], bl[1]);
                    mma_bf16(acc[nb + 1], ah, bh[2], bh[3]);
                    mma_bf16(acc[nb + 1], al, bh[2], bh[3]);
                    mma_bf16(acc[nb + 1], ah, bl[2], bl[3]);
                }
            }
        }

        // epilogue: c0=(g,2t) c1=(g,2t+1) c2=(g+8,2t) c3=(g+8,2t+1)
#pragma unroll
        for (int h = 0; h < 2; h++) {
            int m = tile + wr + g + h * 8;
            if (m < MROWS) {
                float* op;
                if (layer == 0) {
                    op = g_hB + (size_t)m * 128;
                } else {
                    int n = m >> 2;
                    int bt = m & 3;
                    op = out_ext + ((size_t)bt * NNODES + n) * 128;
                }
#pragma unroll
                for (int nb = 0; nb < 4; nb++) {
                    int col = wc + nb * 8 + 2 * t;
                    float2 vv;
                    vv.x = acc[nb][h * 2 + 0] + sbias[col];
                    vv.y = acc[nb][h * 2 + 1] + sbias[col + 1];
                    *(float2*)(op + col) = vv;
                }
            }
        }
        __syncthreads();   // protect s_tile / A buffers before next claim
    }
}

// ---------------- launch ----------------
extern "C" void kernel_launch(void* const* d_in, const int* in_sizes, int n_in,
                              void* d_out, int out_size) {
    const float* feat   = (const float*)d_in[0];
    const float* Wself  = (const float*)d_in[1];
    const float* Wneigh = (const float*)d_in[2];
    const float* bias   = (const float*)d_in[3];
    const int*   esrc   = (const int*)d_in[4];
    const int*   edst   = (const int*)d_in[5];
    int E = in_sizes[4];

    cudaFuncSetAttribute(gemm_mma, cudaFuncAttributeMaxDynamicSharedMemorySize,
                         GSMEM_BYTES);

    void *p_deg, *p_cur, *p_ctr, *p_sync;
    cudaGetSymbolAddress(&p_deg, g_deg);
    cudaGetSymbolAddress(&p_cur, g_cursor);
    cudaGetSymbolAddress(&p_ctr, g_tilectr);
    cudaGetSymbolAddress(&p_sync, g_sync);
    cudaMemsetAsync(p_deg, 0, NNODES * sizeof(int));
    cudaMemsetAsync(p_cur, 0, NNODES * sizeof(int));
    cudaMemsetAsync(p_ctr, 0, 2 * sizeof(int));
    cudaMemsetAsync(p_sync, 0, 2 * sizeof(int));

    // kernel order: wt(1), csr(2), agg0(3), gemm0(4) <- ncu captures #4
    wt_kernel<<<(2 * 128 * 128 + 255) / 256, 256>>>(Wself, Wneigh);
    csr_kernel<<<148, 1024>>>(esrc, edst, E);

    // layer 0: agg(feat) -> g_agg, gemm(feat, agg) -> g_hB
    agg_kernel<<<NNODES, 128>>>(feat, 0);
    gemm_mma<<<148, 512, GSMEM_BYTES>>>(feat, 0, bias, (float*)d_out);

    // layer 1: agg(g_hB) -> g_agg, gemm(g_hB, agg) -> d_out ([B,T,N,F])
    agg_kernel<<<NNODES, 128>>>(feat, 1);
    gemm_mma<<<148, 512, GSMEM_BYTES>>>(feat, 1, bias + 128, (float*)d_out);
}

// round 16
// speedup vs baseline: 1.1746x; 1.0006x over previous
#include <cuda_runtime.h>
#include <cuda_bf16.h>
#include <cstdint>

// Problem constants (fixed shapes for this problem instance)
#define NNODES 10000
#define BT 4            // B*T
#define FDIM 128
#define ROW (BT*FDIM)   // 512 floats per node row
#define EMAX 262144
#define MROWS (NNODES*BT)   // 40000 GEMM rows
#define TILE_M 64
#define NTILES ((MROWS + TILE_M - 1) / TILE_M)   // 625

// GEMM smem layout (32-bit word offsets into dynamic smem)
#define BKS 132                 // row stride in words (128 kpairs + 4 pad)
#define B_HI_OFF 0
#define B_LO_OFF (128*BKS)              // 16896
#define A_HI_OFF (2*128*BKS)            // 33792 (64 rows x BKS, full K)
#define A_LO_OFF (A_HI_OFF + TILE_M*BKS)  // 42240
#define BIAS_OFF (A_LO_OFF + TILE_M*BKS)  // 50688
#define GSMEM_WORDS (BIAS_OFF + 128)    // 50816
#define GSMEM_BYTES (GSMEM_WORDS*4)     // 203264

// ---------------- device scratch (no allocation allowed) ----------------
__device__ float g_hB[NNODES*ROW];
__device__ float g_agg[NNODES*ROW];
__device__ uint32_t g_WThi[2*128*128];  // per layer: [n][kpair] bf16x2 hi plane
__device__ uint32_t g_WTlo[2*128*128];  // per layer: [n][kpair] bf16x2 lo plane
__device__ int   g_deg[NNODES];
__device__ int   g_cursor[NNODES];
__device__ int   g_off[NNODES+1];
__device__ float g_invdeg[NNODES];
__device__ int   g_esrc_sorted[EMAX];
__device__ int   g_tilectr[2];
__device__ int   g_sync[2];

// ---------------- helpers ----------------
__device__ __forceinline__ uint32_t smem_u32(const void* p) {
    uint32_t a;
    asm("{ .reg .u64 t; cvta.to.shared.u64 t, %1; cvt.u32.u64 %0, t; }"
        : "=r"(a) : "l"(p));
    return a;
}

__device__ __forceinline__ void split2(float a, float b, uint32_t& hi, uint32_t& lo) {
    __nv_bfloat16 ha = __float2bfloat16_rn(a);
    __nv_bfloat16 hb = __float2bfloat16_rn(b);
    float ra = a - __bfloat162float(ha);
    float rb = b - __bfloat162float(hb);
    __nv_bfloat16 la = __float2bfloat16_rn(ra);
    __nv_bfloat16 lb = __float2bfloat16_rn(rb);
    hi = ((uint32_t)__bfloat16_as_ushort(hb) << 16) | (uint32_t)__bfloat16_as_ushort(ha);
    lo = ((uint32_t)__bfloat16_as_ushort(lb) << 16) | (uint32_t)__bfloat16_as_ushort(la);
}

__device__ __forceinline__ void mma_bf16(float* c, const uint32_t* a,
                                         uint32_t b0, uint32_t b1) {
    asm volatile(
        "mma.sync.aligned.m16n8k16.row.col.f32.bf16.bf16.f32 "
        "{%0,%1,%2,%3}, {%4,%5,%6,%7}, {%8,%9}, {%0,%1,%2,%3};"
        : "+f"(c[0]), "+f"(c[1]), "+f"(c[2]), "+f"(c[3])
        : "r"(a[0]), "r"(a[1]), "r"(a[2]), "r"(a[3]), "r"(b0), "r"(b1));
}

__device__ __forceinline__ void ldsm4(uint32_t& r0, uint32_t& r1,
                                      uint32_t& r2, uint32_t& r3, uint32_t addr) {
    asm volatile("ldmatrix.sync.aligned.m8n8.x4.shared.b16 {%0,%1,%2,%3}, [%4];"
                 : "=r"(r0), "=r"(r1), "=r"(r2), "=r"(r3) : "r"(addr));
}

// ---------------- setup kernels ----------------
// #1: weight pre-split (independent of edges)
__global__ void wt_kernel(const float* __restrict__ Wself,
                          const float* __restrict__ Wneigh) {
    int idx = blockIdx.x * blockDim.x + threadIdx.x;   // 2*128*128 = 32768 kpairs
    if (idx >= 2 * 128 * 128) return;
    int l = idx >> 14;
    int rem = idx & 16383;
    int n = rem >> 7;
    int kp = rem & 127;
    float w0, w1;
    if (kp < 64) {
        int k = 2 * kp;
        w0 = Wself[l * 16384 + k * 128 + n];
        w1 = Wself[l * 16384 + (k + 1) * 128 + n];
    } else {
        int k = 2 * kp - 128;
        w0 = Wneigh[l * 16384 + k * 128 + n];
        w1 = Wneigh[l * 16384 + (k + 1) * 128 + n];
    }
    uint32_t hi, lo;
    split2(w0, w1, hi, lo);
    g_WThi[idx] = hi;
    g_WTlo[idx] = lo;
}

// #2: fused CSR build: degree -> (grid spin barrier) -> scan (block 0)
//     -> (flag barrier) -> bucket. Grid 148x1024, 1 CTA/SM, all resident.
__global__ void __launch_bounds__(1024) csr_kernel(const int* __restrict__ esrc,
                                                   const int* __restrict__ edst,
                                                   int E) {
    int tid = threadIdx.x;
    int gid = blockIdx.x * 1024 + tid;
    int nthreads = gridDim.x * 1024;
    int n4 = E >> 2;

    // --- phase 1: degree histogram (int4) ---
    for (int j = gid; j < n4; j += nthreads) {
        int4 v = ((const int4*)edst)[j];
        atomicAdd(&g_deg[v.x], 1);
        atomicAdd(&g_deg[v.y], 1);
        atomicAdd(&g_deg[v.z], 1);
        atomicAdd(&g_deg[v.w], 1);
    }
    if (gid == 0) {
        for (int e = n4 * 4; e < E; e++) atomicAdd(&g_deg[edst[e]], 1);
    }
    __threadfence();
    __syncthreads();
    if (tid == 0) {
        atomicAdd(&g_sync[0], 1);
        while (atomicAdd(&g_sync[0], 0) < (int)gridDim.x) __nanosleep(64);
    }
    __syncthreads();

    // --- phase 2: exclusive scan + inv_deg (block 0 only, 1024 threads) ---
    if (blockIdx.x == 0) {
        __shared__ int wsum[32];
        int lane = tid & 31;
        int w = tid >> 5;
        int base = tid * 10;
        int d[10];
        int tot = 0;
#pragma unroll
        for (int j = 0; j < 10; j++) {
            int idx = base + j;
            d[j] = (idx < NNODES) ? g_deg[idx] : 0;
            tot += d[j];
        }
        int inc = tot;
#pragma unroll
        for (int off = 1; off < 32; off <<= 1) {
            int nv = __shfl_up_sync(0xffffffffu, inc, off);
            if (lane >= off) inc += nv;
        }
        if (lane == 31) wsum[w] = inc;
        __syncthreads();
        if (w == 0) {
            int v = wsum[lane];
            int i2 = v;
#pragma unroll
            for (int off = 1; off < 32; off <<= 1) {
                int nv = __shfl_up_sync(0xffffffffu, i2, off);
                if (lane >= off) i2 += nv;
            }
            wsum[lane] = i2 - v;
        }
        __syncthreads();
        int run = wsum[w] + inc - tot;
#pragma unroll
        for (int j = 0; j < 10; j++) {
            int idx = base + j;
            if (idx < NNODES) {
                g_off[idx] = run;
                g_invdeg[idx] = (d[j] > 0) ? (1.0f / (float)d[j]) : 0.0f;
            }
            run += d[j];
        }
        if (tid == 0) g_off[NNODES] = E;
        __threadfence();
        __syncthreads();
        if (tid == 0) atomicExch(&g_sync[1], 1);
    }
    if (tid == 0) {
        while (atomicAdd(&g_sync[1], 0) == 0) __nanosleep(64);
    }
    __syncthreads();

    // --- phase 3: bucket scatter ---
    for (int j = gid; j < n4; j += nthreads) {
        int4 s = ((const int4*)esrc)[j];
        int4 d = ((const int4*)edst)[j];
        int p;
        p = g_off[d.x] + atomicAdd(&g_cursor[d.x], 1); g_esrc_sorted[p] = s.x;
        p = g_off[d.y] + atomicAdd(&g_cursor[d.y], 1); g_esrc_sorted[p] = s.y;
        p = g_off[d.z] + atomicAdd(&g_cursor[d.z], 1); g_esrc_sorted[p] = s.z;
        p = g_off[d.w] + atomicAdd(&g_cursor[d.w], 1); g_esrc_sorted[p] = s.w;
    }
    if (gid == 0) {
        for (int e = n4 * 4; e < E; e++) {
            int dn = edst[e];
            int p = g_off[dn] + atomicAdd(&g_cursor[dn], 1);
            g_esrc_sorted[p] = esrc[e];
        }
    }
}

// ---------------- mean aggregation: one CTA per dst node, 8-wide MLP -----
__global__ void __launch_bounds__(128) agg_kernel(const float* __restrict__ feat,
                                                  int src_sel) {
    int n = blockIdx.x;
    int t = threadIdx.x;
    int s = g_off[n];
    int e = g_off[n + 1];
    float4 a0 = make_float4(0.f, 0.f, 0.f, 0.f);
    float4 a1 = make_float4(0.f, 0.f, 0.f, 0.f);
    float4 a2 = make_float4(0.f, 0.f, 0.f, 0.f);
    float4 a3 = make_float4(0.f, 0.f, 0.f, 0.f);
    int i = s;
    if (src_sel == 0) {
        const float4* hv = (const float4*)feat;
        int bt = t >> 5;
        int f4 = t & 31;
        int boff = bt * NNODES * 32 + f4;
        for (; i + 7 < e; i += 8) {
            int s0 = g_esrc_sorted[i];
            int s1 = g_esrc_sorted[i + 1];
            int s2 = g_esrc_sorted[i + 2];
            int s3 = g_esrc_sorted[i + 3];
            int s4 = g_esrc_sorted[i + 4];
            int s5 = g_esrc_sorted[i + 5];
            int s6 = g_esrc_sorted[i + 6];
            int s7 = g_esrc_sorted[i + 7];
            float4 v0 = hv[boff + s0 * 32];
            float4 v1 = hv[boff + s1 * 32];
            float4 v2 = hv[boff + s2 * 32];
            float4 v3 = hv[boff + s3 * 32];
            float4 v4 = hv[boff + s4 * 32];
            float4 v5 = hv[boff + s5 * 32];
            float4 v6 = hv[boff + s6 * 32];
            float4 v7 = hv[boff + s7 * 32];
            a0.x += v0.x; a0.y += v0.y; a0.z += v0.z; a0.w += v0.w;
            a1.x += v1.x; a1.y += v1.y; a1.z += v1.z; a1.w += v1.w;
            a2.x += v2.x; a2.y += v2.y; a2.z += v2.z; a2.w += v2.w;
            a3.x += v3.x; a3.y += v3.y; a3.z += v3.z; a3.w += v3.w;
            a0.x += v4.x; a0.y += v4.y; a0.z += v4.z; a0.w += v4.w;
            a1.x += v5.x; a1.y += v5.y; a1.z += v5.z; a1.w += v5.w;
            a2.x += v6.x; a2.y += v6.y; a2.z += v6.z; a2.w += v6.w;
            a3.x += v7.x; a3.y += v7.y; a3.z += v7.z; a3.w += v7.w;
        }
        for (; i + 3 < e; i += 4) {
            int s0 = g_esrc_sorted[i];
            int s1 = g_esrc_sorted[i + 1];
            int s2 = g_esrc_sorted[i + 2];
            int s3 = g_esrc_sorted[i + 3];
            float4 v0 = hv[boff + s0 * 32];
            float4 v1 = hv[boff + s1 * 32];
            float4 v2 = hv[boff + s2 * 32];
            float4 v3 = hv[boff + s3 * 32];
            a0.x += v0.x; a0.y += v0.y; a0.z += v0.z; a0.w += v0.w;
            a1.x += v1.x; a1.y += v1.y; a1.z += v1.z; a1.w += v1.w;
            a2.x += v2.x; a2.y += v2.y; a2.z += v2.z; a2.w += v2.w;
            a3.x += v3.x; a3.y += v3.y; a3.z += v3.z; a3.w += v3.w;
        }
        for (; i < e; i++) {
            int s0 = g_esrc_sorted[i];
            float4 v0 = hv[boff + s0 * 32];
            a0.x += v0.x; a0.y += v0.y; a0.z += v0.z; a0.w += v0.w;
        }
    } else {
        const float4* hv = (const float4*)g_hB;
        for (; i + 7 < e; i += 8) {
            int s0 = g_esrc_sorted[i];
            int s1 = g_esrc_sorted[i + 1];
            int s2 = g_esrc_sorted[i + 2];
            int s3 = g_esrc_sorted[i + 3];
            int s4 = g_esrc_sorted[i + 4];
            int s5 = g_esrc_sorted[i + 5];
            int s6 = g_esrc_sorted[i + 6];
            int s7 = g_esrc_sorted[i + 7];
            float4 v0 = hv[s0 * 128 + t];
            float4 v1 = hv[s1 * 128 + t];
            float4 v2 = hv[s2 * 128 + t];
            float4 v3 = hv[s3 * 128 + t];
            float4 v4 = hv[s4 * 128 + t];
            float4 v5 = hv[s5 * 128 + t];
            float4 v6 = hv[s6 * 128 + t];
            float4 v7 = hv[s7 * 128 + t];
            a0.x += v0.x; a0.y += v0.y; a0.z += v0.z; a0.w += v0.w;
            a1.x += v1.x; a1.y += v1.y; a1.z += v1.z; a1.w += v1.w;
            a2.x += v2.x; a2.y += v2.y; a2.z += v2.z; a2.w += v2.w;
            a3.x += v3.x; a3.y += v3.y; a3.z += v3.z; a3.w += v3.w;
            a0.x += v4.x; a0.y += v4.y; a0.z += v4.z; a0.w += v4.w;
            a1.x += v5.x; a1.y += v5.y; a1.z += v5.z; a1.w += v5.w;
            a2.x += v6.x; a2.y += v6.y; a2.z += v6.z; a2.w += v6.w;
            a3.x += v7.x; a3.y += v7.y; a3.z += v7.z; a3.w += v7.w;
        }
        for (; i + 3 < e; i += 4) {
            int s0 = g_esrc_sorted[i];
            int s1 = g_esrc_sorted[i + 1];
            int s2 = g_esrc_sorted[i + 2];
            int s3 = g_esrc_sorted[i + 3];
            float4 v0 = hv[s0 * 128 + t];
            float4 v1 = hv[s1 * 128 + t];
            float4 v2 = hv[s2 * 128 + t];
            float4 v3 = hv[s3 * 128 + t];
            a0.x += v0.x; a0.y += v0.y; a0.z += v0.z; a0.w += v0.w;
            a1.x += v1.x; a1.y += v1.y; a1.z += v1.z; a1.w += v1.w;
            a2.x += v2.x; a2.y += v2.y; a2.z += v2.z; a2.w += v2.w;
            a3.x += v3.x; a3.y += v3.y; a3.z += v3.z; a3.w += v3.w;
        }
        for (; i < e; i++) {
            int s0 = g_esrc_sorted[i];
            float4 v0 = hv[s0 * 128 + t];
            a0.x += v0.x; a0.y += v0.y; a0.z += v0.z; a0.w += v0.w;
        }
    }
    float inv = g_invdeg[n];
    float4 r;
    r.x = (a0.x + a1.x + a2.x + a3.x) * inv;
    r.y = (a0.y + a1.y + a2.y + a3.y) * inv;
    r.z = (a0.z + a1.z + a2.z + a3.z) * inv;
    r.w = (a0.w + a1.w + a2.w + a3.w) * inv;
    ((float4*)g_agg)[n * 128 + t] = r;
}

// ---------------- persistent mma.sync bf16x2-split GEMM ------------------
// out[m][n] = sum_k X[m][k]*W[k][n] + b[n]; M=40000, K=256, N=128.
// 64x128 tiles; FULL-K A staging (8 float4/thread in flight), ONE barrier
// per tile, then 16 ksteps of MMA barrier-free.
__global__ void __launch_bounds__(512) gemm_mma(const float* __restrict__ feat,
                                                int layer,
                                                const float* __restrict__ bias,
                                                float* __restrict__ out_ext) {
    extern __shared__ uint32_t sm[];
    __shared__ int s_tile;
    uint32_t* Bhi = sm + B_HI_OFF;
    uint32_t* Blo = sm + B_LO_OFF;
    uint32_t* Ahi = sm + A_HI_OFF;
    uint32_t* Alo = sm + A_LO_OFF;
    float* sbias = (float*)(sm + BIAS_OFF);

    int tid = threadIdx.x;
    int lane = tid & 31;
    int warp = tid >> 5;
    int g = lane >> 2;
    int t = lane & 3;
    int wr = (warp & 3) * 16;      // 4 row groups of 16
    int wc = (warp >> 2) * 32;     // 4 col groups of 32
    uint32_t smbase = smem_u32(sm);

    // ldmatrix lane address components (word offsets); row stride = BKS
    int am = lane >> 3;
    int ar = lane & 7;
    int a_base = (wr + ((am & 1) << 3) + ar) * BKS + ((am >> 1) << 2);
    int b_base = (wc + ((lane >> 4) << 3) + ar) * BKS + (((lane >> 3) & 1) << 2);

    if (tid < 128) sbias[tid] = bias[tid];

    // stage B once: straight uint4 copy of pre-split planes (4096 uint4/plane)
    const uint4* bhv = (const uint4*)(g_WThi + layer * 128 * 128);
    const uint4* blv = (const uint4*)(g_WTlo + layer * 128 * 128);
#pragma unroll
    for (int i = 0; i < 8; i++) {
        int lin = tid + i * 512;
        int n = lin >> 5;
        int j = lin & 31;
        *(uint4*)&Bhi[n * BKS + 4 * j] = bhv[lin];
        *(uint4*)&Blo[n * BKS + 4 * j] = blv[lin];
    }

    const float4* x0v = (layer == 0) ? (const float4*)feat : (const float4*)g_hB;
    const float4* x1v = (const float4*)g_agg;

    uint32_t ahi_addr = smbase + 4u * (A_HI_OFF + a_base);
    uint32_t alo_addr = smbase + 4u * (A_LO_OFF + a_base);

    while (true) {
        if (tid == 0) s_tile = atomicAdd(&g_tilectr[layer], 1);
        __syncthreads();
        int tnum = s_tile;
        if (tnum >= NTILES) break;
        int tile = tnum * TILE_M;

        // load ALL of A for this tile: 4096 float4 = 8 per thread, issued
        // back-to-back for maximum MLP (64 rows x 64 float4 per row).
        float4 v[8];
#pragma unroll
        for (int i = 0; i < 8; i++) {
            int lin = tid + i * 512;
            int row = lin >> 6;
            int j = lin & 63;          // float4 index within row (k4 global)
            int m = tile + row;
            if (m >= MROWS) m = MROWS - 1;
            if (j < 32) {
                if (layer == 0) {
                    int node = m >> 2;
                    int bt = m & 3;
                    v[i] = x0v[(bt * NNODES + node) * 32 + j];
                } else {
                    v[i] = x0v[m * 32 + j];
                }
            } else {
                v[i] = x1v[m * 32 + (j - 32)];
            }
        }

        float acc[4][4];
#pragma unroll
        for (int nb = 0; nb < 4; nb++)
#pragma unroll
            for (int c = 0; c < 4; c++) acc[nb][c] = 0.f;

        // split & store all of A
#pragma unroll
        for (int i = 0; i < 8; i++) {
            int lin = tid + i * 512;
            int row = lin >> 6;
            int j = lin & 63;
            uint32_t h0, l0, h1, l1;
            split2(v[i].x, v[i].y, h0, l0);
            split2(v[i].z, v[i].w, h1, l1);
            *(uint2*)&Ahi[row * BKS + 2 * j] = make_uint2(h0, h1);
            *(uint2*)&Alo[row * BKS + 2 * j] = make_uint2(l0, l1);
        }
        __syncthreads();

        // full-K MMA run, barrier-free: 16 ksteps
#pragma unroll 4
        for (int gk = 0; gk < 16; gk++) {
            int kb = gk * 8;               // kpair base
            uint32_t off = 4u * kb;
            uint32_t ah[4], al[4];
            ldsm4(ah[0], ah[1], ah[2], ah[3], ahi_addr + off);
            ldsm4(al[0], al[1], al[2], al[3], alo_addr + off);
#pragma unroll
            for (int nb = 0; nb < 4; nb += 2) {
                uint32_t bw = smbase + 4u * (b_base + nb * 8 * BKS + kb);
                uint32_t bh[4], bl[4];
                ldsm4(bh[0], bh[1], bh[2], bh[3], bw + 4u * B_HI_OFF);
                ldsm4(bl[0], bl[1], bl[2], bl[3], bw + 4u * B_LO_OFF);
                mma_bf16(acc[nb], ah, bh[0], bh[1]);
                mma_bf16(acc[nb], al, bh[0], bh[1]);
                mma_bf16(acc[nb], ah, bl[0], bl[1]);
                mma_bf16(acc[nb + 1], ah, bh[2], bh[3]);
                mma_bf16(acc[nb + 1], al, bh[2], bh[3]);
                mma_bf16(acc[nb + 1], ah, bl[2], bl[3]);
            }
        }

        // epilogue: c0=(g,2t) c1=(g,2t+1) c2=(g+8,2t) c3=(g+8,2t+1)
#pragma unroll
        for (int h = 0; h < 2; h++) {
            int m = tile + wr + g + h * 8;
            if (m < MROWS) {
                float* op;
                if (layer == 0) {
                    op = g_hB + (size_t)m * 128;
                } else {
                    int n = m >> 2;
                    int bt = m & 3;
                    op = out_ext + ((size_t)bt * NNODES + n) * 128;
                }
#pragma unroll
                for (int nb = 0; nb < 4; nb++) {
                    int col = wc + nb * 8 + 2 * t;
                    float2 vv;
                    vv.x = acc[nb][h * 2 + 0] + sbias[col];
                    vv.y = acc[nb][h * 2 + 1] + sbias[col + 1];
                    *(float2*)(op + col) = vv;
                }
            }
        }
        __syncthreads();   // protect s_tile / A buffer before next claim
    }
}

// ---------------- launch ----------------
extern "C" void kernel_launch(void* const* d_in, const int* in_sizes, int n_in,
                              void* d_out, int out_size) {
    const float* feat   = (const float*)d_in[0];
    const float* Wself  = (const float*)d_in[1];
    const float* Wneigh = (const float*)d_in[2];
    const float* bias   = (const float*)d_in[3];
    const int*   esrc   = (const int*)d_in[4];
    const int*   edst   = (const int*)d_in[5];
    int E = in_sizes[4];

    cudaFuncSetAttribute(gemm_mma, cudaFuncAttributeMaxDynamicSharedMemorySize,
                         GSMEM_BYTES);

    void *p_deg, *p_cur, *p_ctr, *p_sync;
    cudaGetSymbolAddress(&p_deg, g_deg);
    cudaGetSymbolAddress(&p_cur, g_cursor);
    cudaGetSymbolAddress(&p_ctr, g_tilectr);
    cudaGetSymbolAddress(&p_sync, g_sync);
    cudaMemsetAsync(p_deg, 0, NNODES * sizeof(int));
    cudaMemsetAsync(p_cur, 0, NNODES * sizeof(int));
    cudaMemsetAsync(p_ctr, 0, 2 * sizeof(int));
    cudaMemsetAsync(p_sync, 0, 2 * sizeof(int));

    // kernel order: wt(1), csr(2), agg0(3), gemm0(4) <- ncu captures #4
    wt_kernel<<<(2 * 128 * 128 + 255) / 256, 256>>>(Wself, Wneigh);
    csr_kernel<<<148, 1024>>>(esrc, edst, E);

    // layer 0: agg(feat) -> g_agg, gemm(feat, agg) -> g_hB
    agg_kernel<<<NNODES, 128>>>(feat, 0);
    gemm_mma<<<148, 512, GSMEM_BYTES>>>(feat, 0, bias, (float*)d_out);

    // layer 1: agg(g_hB) -> g_agg, gemm(g_hB, agg) -> d_out ([B,T,N,F])
    agg_kernel<<<NNODES, 128>>>(feat, 1);
    gemm_mma<<<148, 512, GSMEM_BYTES>>>(feat, 1, bias + 128, (float*)d_out);
}